// round 1
// baseline (speedup 1.0000x reference)
#include <cuda_runtime.h>

// ---------------------------------------------------------------------------
// DiagonnalyMaskedSelfAttention: B=2, L=2048, DIM=1024, H=16, D=64, fp32.
// Pipeline: qkv_gemm -> flash-attention (diag mask) -> out_gemm.
// All scratch in __device__ globals (no allocations; graph-capturable).
// ---------------------------------------------------------------------------

#define KB   2
#define KL   2048
#define KDIM 1024
#define KH   16
#define KD   64
#define KM   (KB * KL)   // 4096 rows

__device__ float g_q[KB * KH * KL * KD];     // [b,h,l,d]
__device__ float g_k[KB * KH * KL * KD];
__device__ float g_v[KB * KH * KL * KD];
__device__ float g_attn[KM * KDIM];          // [b*l, h*d]

// ---------------------------------------------------------------------------
// Tiled fp32 GEMM: C[64x64] tile per block, BK=16, 256 threads, 4x4 micro-tile
// ---------------------------------------------------------------------------

__global__ __launch_bounds__(256) void qkv_gemm(
    const float* __restrict__ x,
    const float* __restrict__ Wq,
    const float* __restrict__ Wk,
    const float* __restrict__ Wv)
{
    __shared__ float As[16][68];   // A tile transposed: As[k][m]
    __shared__ float Bs[16][64];   // B tile natural:    Bs[k][n]

    const float* W = (blockIdx.z == 0) ? Wq : (blockIdx.z == 1 ? Wk : Wv);
    float* out     = (blockIdx.z == 0) ? g_q : (blockIdx.z == 1 ? g_k : g_v);

    const int tid = threadIdx.x;
    const int tx  = tid & 15;
    const int ty  = tid >> 4;
    const int m0  = blockIdx.y << 6;
    const int n0  = blockIdx.x << 6;

    const int ar = tid >> 2;          // 0..63  A row within tile
    const int ac = (tid & 3) << 2;    // 0,4,8,12  A k-col group
    const int br = tid >> 4;          // 0..15  B k-row
    const int bc = (tid & 15) << 2;   // B col group

    float acc[4][4];
    #pragma unroll
    for (int i = 0; i < 4; i++)
        #pragma unroll
        for (int j = 0; j < 4; j++) acc[i][j] = 0.f;

    for (int k0 = 0; k0 < KDIM; k0 += 16) {
        const float4 av = *reinterpret_cast<const float4*>(
            x + (size_t)(m0 + ar) * KDIM + k0 + ac);
        const float4 bv = *reinterpret_cast<const float4*>(
            W + (size_t)(k0 + br) * KDIM + n0 + bc);
        __syncthreads();
        As[ac + 0][ar] = av.x;
        As[ac + 1][ar] = av.y;
        As[ac + 2][ar] = av.z;
        As[ac + 3][ar] = av.w;
        *reinterpret_cast<float4*>(&Bs[br][bc]) = bv;
        __syncthreads();
        #pragma unroll
        for (int k = 0; k < 16; k++) {
            const float4 a = *reinterpret_cast<const float4*>(&As[k][ty << 2]);
            const float4 b = *reinterpret_cast<const float4*>(&Bs[k][tx << 2]);
            const float aa[4] = {a.x, a.y, a.z, a.w};
            const float bb[4] = {b.x, b.y, b.z, b.w};
            #pragma unroll
            for (int i = 0; i < 4; i++)
                #pragma unroll
                for (int j = 0; j < 4; j++) acc[i][j] += aa[i] * bb[j];
        }
    }

    // Write in [b,h,l,d] layout
    #pragma unroll
    for (int i = 0; i < 4; i++) {
        const int m = m0 + (ty << 2) + i;
        const int bidx = m / KL;
        const int l    = m % KL;
        #pragma unroll
        for (int j = 0; j < 4; j++) {
            const int n = n0 + (tx << 2) + j;
            const int h = n >> 6;
            const int d = n & 63;
            out[(((size_t)bidx * KH + h) * KL + l) * KD + d] = acc[i][j];
        }
    }
}

__global__ __launch_bounds__(256) void out_gemm(
    const float* __restrict__ Wo,
    float* __restrict__ out)
{
    __shared__ float As[16][68];
    __shared__ float Bs[16][64];

    const int tid = threadIdx.x;
    const int tx  = tid & 15;
    const int ty  = tid >> 4;
    const int m0  = blockIdx.y << 6;
    const int n0  = blockIdx.x << 6;

    const int ar = tid >> 2;
    const int ac = (tid & 3) << 2;
    const int br = tid >> 4;
    const int bc = (tid & 15) << 2;

    float acc[4][4];
    #pragma unroll
    for (int i = 0; i < 4; i++)
        #pragma unroll
        for (int j = 0; j < 4; j++) acc[i][j] = 0.f;

    for (int k0 = 0; k0 < KDIM; k0 += 16) {
        const float4 av = *reinterpret_cast<const float4*>(
            g_attn + (size_t)(m0 + ar) * KDIM + k0 + ac);
        const float4 bv = *reinterpret_cast<const float4*>(
            Wo + (size_t)(k0 + br) * KDIM + n0 + bc);
        __syncthreads();
        As[ac + 0][ar] = av.x;
        As[ac + 1][ar] = av.y;
        As[ac + 2][ar] = av.z;
        As[ac + 3][ar] = av.w;
        *reinterpret_cast<float4*>(&Bs[br][bc]) = bv;
        __syncthreads();
        #pragma unroll
        for (int k = 0; k < 16; k++) {
            const float4 a = *reinterpret_cast<const float4*>(&As[k][ty << 2]);
            const float4 b = *reinterpret_cast<const float4*>(&Bs[k][tx << 2]);
            const float aa[4] = {a.x, a.y, a.z, a.w};
            const float bb[4] = {b.x, b.y, b.z, b.w};
            #pragma unroll
            for (int i = 0; i < 4; i++)
                #pragma unroll
                for (int j = 0; j < 4; j++) acc[i][j] += aa[i] * bb[j];
        }
    }

    #pragma unroll
    for (int i = 0; i < 4; i++) {
        const int m = m0 + (ty << 2) + i;
        #pragma unroll
        for (int j = 0; j < 4; j++) {
            const int n = n0 + (tx << 2) + j;
            out[(size_t)m * KDIM + n] = acc[i][j];
        }
    }
}

// ---------------------------------------------------------------------------
// Flash attention with diagonal self-mask.
// One block = 64 query rows of one (b,h). 256 threads, 4x4 micro-tiles.
// SMEM (dynamic, ~55KB): Qs[64][68] (transposed, pre-scaled), Ks[64][68]
// (transposed; aliased as Ps after S is computed), Vs[64][64], reduction buf.
// ---------------------------------------------------------------------------

#define QS_STRIDE 68
#define ATTN_SMEM_FLOATS (64 * 68 * 2 + 64 * 64 + 64 * 17 + 3 * 64)

__global__ __launch_bounds__(256) void attn_kernel()
{
    extern __shared__ float sm[];
    float* Qs  = sm;                     // [64][68]  Qs[d][r]
    float* Ks  = Qs + 64 * QS_STRIDE;    // [64][68]  Ks[d][c]  (aliased as Ps[k][r])
    float* Vs  = Ks + 64 * QS_STRIDE;    // [64][64]  Vs[k][d]
    float* red = Vs + 64 * 64;           // [64][17]
    float* m_s = red + 64 * 17;          // [64] running max
    float* a_s = m_s + 64;               // [64] alpha
    float* l_s = a_s + 64;               // [64] running sum

    const int tid = threadIdx.x;
    const int tx  = tid & 15;
    const int ty  = tid >> 4;
    const int r0  = ty << 2;             // query-row base within tile
    const int c0  = tx << 2;             // kv-col / d-col base

    const int bid = blockIdx.x;
    const int qt  = bid & 31;            // 32 query tiles per head
    const int bh  = bid >> 5;            // 0..31 (b*16+h)
    const int l0q = qt << 6;
    const int b   = bh >> 4;
    const int h   = bh & 15;

    const float* qptr = g_q + (size_t)bh * KL * KD;
    const float* kptr = g_k + (size_t)bh * KL * KD;
    const float* vptr = g_v + (size_t)bh * KL * KD;

    const float scale = 0.125f;          // 1/sqrt(64)

    // Load Q tile, pre-scaled, transposed -> Qs[d][r]
    #pragma unroll
    for (int p = 0; p < 4; p++) {
        const int idx = tid + (p << 8);
        const int row = idx >> 4;
        const int c4  = (idx & 15) << 2;
        const float4 v = *reinterpret_cast<const float4*>(
            qptr + (size_t)(l0q + row) * KD + c4);
        Qs[(c4 + 0) * QS_STRIDE + row] = v.x * scale;
        Qs[(c4 + 1) * QS_STRIDE + row] = v.y * scale;
        Qs[(c4 + 2) * QS_STRIDE + row] = v.z * scale;
        Qs[(c4 + 3) * QS_STRIDE + row] = v.w * scale;
    }
    if (tid < 64) { m_s[tid] = -1e30f; l_s[tid] = 0.f; }

    float o[4][4];
    #pragma unroll
    for (int i = 0; i < 4; i++)
        #pragma unroll
        for (int j = 0; j < 4; j++) o[i][j] = 0.f;

    for (int kt = 0; kt < 32; kt++) {
        const int l0k = kt << 6;
        __syncthreads();   // prior Ps/Vs reads complete before overwrite

        // Load K transposed -> Ks[d][c], V natural -> Vs[k][d]
        #pragma unroll
        for (int p = 0; p < 4; p++) {
            const int idx = tid + (p << 8);
            const int row = idx >> 4;
            const int c4  = (idx & 15) << 2;
            const float4 kv = *reinterpret_cast<const float4*>(
                kptr + (size_t)(l0k + row) * KD + c4);
            Ks[(c4 + 0) * QS_STRIDE + row] = kv.x;
            Ks[(c4 + 1) * QS_STRIDE + row] = kv.y;
            Ks[(c4 + 2) * QS_STRIDE + row] = kv.z;
            Ks[(c4 + 3) * QS_STRIDE + row] = kv.w;
            const float4 vv = *reinterpret_cast<const float4*>(
                vptr + (size_t)(l0k + row) * KD + c4);
            *reinterpret_cast<float4*>(&Vs[row * 64 + c4]) = vv;
        }
        __syncthreads();

        // S = (Q*scale) K^T  for this 64x64 tile
        float s[4][4];
        #pragma unroll
        for (int i = 0; i < 4; i++)
            #pragma unroll
            for (int j = 0; j < 4; j++) s[i][j] = 0.f;

        #pragma unroll 8
        for (int d = 0; d < 64; d++) {
            const float4 a = *reinterpret_cast<const float4*>(&Qs[d * QS_STRIDE + r0]);
            const float4 bq = *reinterpret_cast<const float4*>(&Ks[d * QS_STRIDE + c0]);
            const float aa[4] = {a.x, a.y, a.z, a.w};
            const float bb[4] = {bq.x, bq.y, bq.z, bq.w};
            #pragma unroll
            for (int i = 0; i < 4; i++)
                #pragma unroll
                for (int j = 0; j < 4; j++) s[i][j] += aa[i] * bb[j];
        }

        // Diagonal self-mask (query index == key index)
        if (l0q == l0k) {
            #pragma unroll
            for (int i = 0; i < 4; i++)
                #pragma unroll
                for (int j = 0; j < 4; j++)
                    if (r0 + i == c0 + j) s[i][j] = -1e30f;
        }

        // Row-max partials -> reduce by 64 threads
        #pragma unroll
        for (int i = 0; i < 4; i++) {
            const float pm = fmaxf(fmaxf(s[i][0], s[i][1]), fmaxf(s[i][2], s[i][3]));
            red[(r0 + i) * 17 + tx] = pm;
        }
        __syncthreads();
        if (tid < 64) {
            float mx = -1e30f;
            #pragma unroll
            for (int t = 0; t < 16; t++) mx = fmaxf(mx, red[tid * 17 + t]);
            const float mo = m_s[tid];
            const float mn = fmaxf(mo, mx);
            m_s[tid] = mn;
            a_s[tid] = __expf(mo - mn);
        }
        __syncthreads();

        // P = exp(S - m_new), store transposed into Ps (aliases Ks), rowsum
        float* Ps = Ks;
        float psum[4] = {0.f, 0.f, 0.f, 0.f};
        #pragma unroll
        for (int i = 0; i < 4; i++) {
            const float mn = m_s[r0 + i];
            #pragma unroll
            for (int j = 0; j < 4; j++) {
                const float p = __expf(s[i][j] - mn);
                psum[i] += p;
                Ps[(c0 + j) * QS_STRIDE + (r0 + i)] = p;
            }
        }
        #pragma unroll
        for (int i = 0; i < 4; i++) red[(r0 + i) * 17 + tx] = psum[i];
        __syncthreads();
        if (tid < 64) {
            float ss = 0.f;
            #pragma unroll
            for (int t = 0; t < 16; t++) ss += red[tid * 17 + t];
            l_s[tid] = l_s[tid] * a_s[tid] + ss;
        }

        // O = O*alpha + P @ V
        #pragma unroll
        for (int i = 0; i < 4; i++) {
            const float al = a_s[r0 + i];
            #pragma unroll
            for (int j = 0; j < 4; j++) o[i][j] *= al;
        }
        #pragma unroll 8
        for (int k = 0; k < 64; k++) {
            const float4 a = *reinterpret_cast<const float4*>(&Ps[k * QS_STRIDE + r0]);
            const float4 bv = *reinterpret_cast<const float4*>(&Vs[k * 64 + c0]);
            const float aa[4] = {a.x, a.y, a.z, a.w};
            const float bb[4] = {bv.x, bv.y, bv.z, bv.w};
            #pragma unroll
            for (int i = 0; i < 4; i++)
                #pragma unroll
                for (int j = 0; j < 4; j++) o[i][j] += aa[i] * bb[j];
        }
    }

    __syncthreads();   // l_s final
    #pragma unroll
    for (int i = 0; i < 4; i++) {
        const float inv = 1.f / l_s[r0 + i];
        const int l = l0q + r0 + i;
        #pragma unroll
        for (int j = 0; j < 4; j++) {
            g_attn[((size_t)(b * KL + l)) * KDIM + h * KD + c0 + j] = o[i][j] * inv;
        }
    }
}

// ---------------------------------------------------------------------------

extern "C" void kernel_launch(void* const* d_in, const int* in_sizes, int n_in,
                              void* d_out, int out_size)
{
    const float* x  = (const float*)d_in[0];
    const float* Wq = (const float*)d_in[1];
    const float* Wk = (const float*)d_in[2];
    const float* Wv = (const float*)d_in[3];
    const float* Wo = (const float*)d_in[4];
    float* out = (float*)d_out;

    const size_t attn_smem = (size_t)ATTN_SMEM_FLOATS * sizeof(float);
    cudaFuncSetAttribute(attn_kernel,
                         cudaFuncAttributeMaxDynamicSharedMemorySize,
                         (int)attn_smem);

    dim3 g_qkv(KDIM / 64, KM / 64, 3);
    qkv_gemm<<<g_qkv, 256>>>(x, Wq, Wk, Wv);

    attn_kernel<<<KB * KH * (KL / 64), 256, attn_smem>>>();

    dim3 g_out(KDIM / 64, KM / 64);
    out_gemm<<<g_out, 256>>>(Wo, out);
}

// round 2
// speedup vs baseline: 1.0006x; 1.0006x over previous
#include <cuda_runtime.h>

// ---------------------------------------------------------------------------
// DiagonnalyMaskedSelfAttention: B=2, L=2048, DIM=1024, H=16, D=64, fp32.
// Pipeline: qkv_gemm -> flash-attention (diag mask) -> out_gemm.
// All scratch in __device__ globals (no allocations; graph-capturable).
// ---------------------------------------------------------------------------

#define KB   2
#define KL   2048
#define KDIM 1024
#define KH   16
#define KD   64
#define KM   (KB * KL)   // 4096 rows

__device__ float g_q[KB * KH * KL * KD];     // [b,h,l,d]
__device__ float g_k[KB * KH * KL * KD];
__device__ float g_v[KB * KH * KL * KD];
__device__ float g_attn[KM * KDIM];          // [b*l, h*d]

// ---------------------------------------------------------------------------
// Tiled fp32 GEMM: C[64x64] tile per block, BK=16, 256 threads, 4x4 micro-tile
// ---------------------------------------------------------------------------

__global__ __launch_bounds__(256) void qkv_gemm(
    const float* __restrict__ x,
    const float* __restrict__ Wq,
    const float* __restrict__ Wk,
    const float* __restrict__ Wv)
{
    __shared__ float As[16][68];   // A tile transposed: As[k][m]
    __shared__ float Bs[16][64];   // B tile natural:    Bs[k][n]

    const float* W = (blockIdx.z == 0) ? Wq : (blockIdx.z == 1 ? Wk : Wv);
    float* out     = (blockIdx.z == 0) ? g_q : (blockIdx.z == 1 ? g_k : g_v);

    const int tid = threadIdx.x;
    const int tx  = tid & 15;
    const int ty  = tid >> 4;
    const int m0  = blockIdx.y << 6;
    const int n0  = blockIdx.x << 6;

    const int ar = tid >> 2;          // 0..63  A row within tile
    const int ac = (tid & 3) << 2;    // 0,4,8,12  A k-col group
    const int br = tid >> 4;          // 0..15  B k-row
    const int bc = (tid & 15) << 2;   // B col group

    float acc[4][4];
    #pragma unroll
    for (int i = 0; i < 4; i++)
        #pragma unroll
        for (int j = 0; j < 4; j++) acc[i][j] = 0.f;

    for (int k0 = 0; k0 < KDIM; k0 += 16) {
        const float4 av = *reinterpret_cast<const float4*>(
            x + (size_t)(m0 + ar) * KDIM + k0 + ac);
        const float4 bv = *reinterpret_cast<const float4*>(
            W + (size_t)(k0 + br) * KDIM + n0 + bc);
        __syncthreads();
        As[ac + 0][ar] = av.x;
        As[ac + 1][ar] = av.y;
        As[ac + 2][ar] = av.z;
        As[ac + 3][ar] = av.w;
        *reinterpret_cast<float4*>(&Bs[br][bc]) = bv;
        __syncthreads();
        #pragma unroll
        for (int k = 0; k < 16; k++) {
            const float4 a = *reinterpret_cast<const float4*>(&As[k][ty << 2]);
            const float4 b = *reinterpret_cast<const float4*>(&Bs[k][tx << 2]);
            const float aa[4] = {a.x, a.y, a.z, a.w};
            const float bb[4] = {b.x, b.y, b.z, b.w};
            #pragma unroll
            for (int i = 0; i < 4; i++)
                #pragma unroll
                for (int j = 0; j < 4; j++) acc[i][j] += aa[i] * bb[j];
        }
    }

    // Write in [b,h,l,d] layout
    #pragma unroll
    for (int i = 0; i < 4; i++) {
        const int m = m0 + (ty << 2) + i;
        const int bidx = m / KL;
        const int l    = m % KL;
        #pragma unroll
        for (int j = 0; j < 4; j++) {
            const int n = n0 + (tx << 2) + j;
            const int h = n >> 6;
            const int d = n & 63;
            out[(((size_t)bidx * KH + h) * KL + l) * KD + d] = acc[i][j];
        }
    }
}

__global__ __launch_bounds__(256) void out_gemm(
    const float* __restrict__ Wo,
    float* __restrict__ out)
{
    __shared__ float As[16][68];
    __shared__ float Bs[16][64];

    const int tid = threadIdx.x;
    const int tx  = tid & 15;
    const int ty  = tid >> 4;
    const int m0  = blockIdx.y << 6;
    const int n0  = blockIdx.x << 6;

    const int ar = tid >> 2;
    const int ac = (tid & 3) << 2;
    const int br = tid >> 4;
    const int bc = (tid & 15) << 2;

    float acc[4][4];
    #pragma unroll
    for (int i = 0; i < 4; i++)
        #pragma unroll
        for (int j = 0; j < 4; j++) acc[i][j] = 0.f;

    for (int k0 = 0; k0 < KDIM; k0 += 16) {
        const float4 av = *reinterpret_cast<const float4*>(
            g_attn + (size_t)(m0 + ar) * KDIM + k0 + ac);
        const float4 bv = *reinterpret_cast<const float4*>(
            Wo + (size_t)(k0 + br) * KDIM + n0 + bc);
        __syncthreads();
        As[ac + 0][ar] = av.x;
        As[ac + 1][ar] = av.y;
        As[ac + 2][ar] = av.z;
        As[ac + 3][ar] = av.w;
        *reinterpret_cast<float4*>(&Bs[br][bc]) = bv;
        __syncthreads();
        #pragma unroll
        for (int k = 0; k < 16; k++) {
            const float4 a = *reinterpret_cast<const float4*>(&As[k][ty << 2]);
            const float4 b = *reinterpret_cast<const float4*>(&Bs[k][tx << 2]);
            const float aa[4] = {a.x, a.y, a.z, a.w};
            const float bb[4] = {b.x, b.y, b.z, b.w};
            #pragma unroll
            for (int i = 0; i < 4; i++)
                #pragma unroll
                for (int j = 0; j < 4; j++) acc[i][j] += aa[i] * bb[j];
        }
    }

    #pragma unroll
    for (int i = 0; i < 4; i++) {
        const int m = m0 + (ty << 2) + i;
        #pragma unroll
        for (int j = 0; j < 4; j++) {
            const int n = n0 + (tx << 2) + j;
            out[(size_t)m * KDIM + n] = acc[i][j];
        }
    }
}

// ---------------------------------------------------------------------------
// Flash attention with diagonal self-mask.
// One block = 64 query rows of one (b,h). 256 threads, 4x4 micro-tiles.
// SMEM (dynamic, ~55KB): Qs[64][68] (transposed, pre-scaled), Ks[64][68]
// (transposed; aliased as Ps after S is computed), Vs[64][64], reduction buf.
// ---------------------------------------------------------------------------

#define QS_STRIDE 68
#define ATTN_SMEM_FLOATS (64 * 68 * 2 + 64 * 64 + 64 * 17 + 3 * 64)

__global__ __launch_bounds__(256) void attn_kernel()
{
    extern __shared__ float sm[];
    float* Qs  = sm;                     // [64][68]  Qs[d][r]
    float* Ks  = Qs + 64 * QS_STRIDE;    // [64][68]  Ks[d][c]  (aliased as Ps[k][r])
    float* Vs  = Ks + 64 * QS_STRIDE;    // [64][64]  Vs[k][d]
    float* red = Vs + 64 * 64;           // [64][17]
    float* m_s = red + 64 * 17;          // [64] running max
    float* a_s = m_s + 64;               // [64] alpha
    float* l_s = a_s + 64;               // [64] running sum

    const int tid = threadIdx.x;
    const int tx  = tid & 15;
    const int ty  = tid >> 4;
    const int r0  = ty << 2;             // query-row base within tile
    const int c0  = tx << 2;             // kv-col / d-col base

    const int bid = blockIdx.x;
    const int qt  = bid & 31;            // 32 query tiles per head
    const int bh  = bid >> 5;            // 0..31 (b*16+h)
    const int l0q = qt << 6;
    const int b   = bh >> 4;
    const int h   = bh & 15;

    const float* qptr = g_q + (size_t)bh * KL * KD;
    const float* kptr = g_k + (size_t)bh * KL * KD;
    const float* vptr = g_v + (size_t)bh * KL * KD;

    const float scale = 0.125f;          // 1/sqrt(64)

    // Load Q tile, pre-scaled, transposed -> Qs[d][r]
    #pragma unroll
    for (int p = 0; p < 4; p++) {
        const int idx = tid + (p << 8);
        const int row = idx >> 4;
        const int c4  = (idx & 15) << 2;
        const float4 v = *reinterpret_cast<const float4*>(
            qptr + (size_t)(l0q + row) * KD + c4);
        Qs[(c4 + 0) * QS_STRIDE + row] = v.x * scale;
        Qs[(c4 + 1) * QS_STRIDE + row] = v.y * scale;
        Qs[(c4 + 2) * QS_STRIDE + row] = v.z * scale;
        Qs[(c4 + 3) * QS_STRIDE + row] = v.w * scale;
    }
    if (tid < 64) { m_s[tid] = -1e30f; l_s[tid] = 0.f; }

    float o[4][4];
    #pragma unroll
    for (int i = 0; i < 4; i++)
        #pragma unroll
        for (int j = 0; j < 4; j++) o[i][j] = 0.f;

    for (int kt = 0; kt < 32; kt++) {
        const int l0k = kt << 6;
        __syncthreads();   // prior Ps/Vs reads complete before overwrite

        // Load K transposed -> Ks[d][c], V natural -> Vs[k][d]
        #pragma unroll
        for (int p = 0; p < 4; p++) {
            const int idx = tid + (p << 8);
            const int row = idx >> 4;
            const int c4  = (idx & 15) << 2;
            const float4 kv = *reinterpret_cast<const float4*>(
                kptr + (size_t)(l0k + row) * KD + c4);
            Ks[(c4 + 0) * QS_STRIDE + row] = kv.x;
            Ks[(c4 + 1) * QS_STRIDE + row] = kv.y;
            Ks[(c4 + 2) * QS_STRIDE + row] = kv.z;
            Ks[(c4 + 3) * QS_STRIDE + row] = kv.w;
            const float4 vv = *reinterpret_cast<const float4*>(
                vptr + (size_t)(l0k + row) * KD + c4);
            *reinterpret_cast<float4*>(&Vs[row * 64 + c4]) = vv;
        }
        __syncthreads();

        // S = (Q*scale) K^T  for this 64x64 tile
        float s[4][4];
        #pragma unroll
        for (int i = 0; i < 4; i++)
            #pragma unroll
            for (int j = 0; j < 4; j++) s[i][j] = 0.f;

        #pragma unroll 8
        for (int d = 0; d < 64; d++) {
            const float4 a = *reinterpret_cast<const float4*>(&Qs[d * QS_STRIDE + r0]);
            const float4 bq = *reinterpret_cast<const float4*>(&Ks[d * QS_STRIDE + c0]);
            const float aa[4] = {a.x, a.y, a.z, a.w};
            const float bb[4] = {bq.x, bq.y, bq.z, bq.w};
            #pragma unroll
            for (int i = 0; i < 4; i++)
                #pragma unroll
                for (int j = 0; j < 4; j++) s[i][j] += aa[i] * bb[j];
        }

        // Diagonal self-mask (query index == key index)
        if (l0q == l0k) {
            #pragma unroll
            for (int i = 0; i < 4; i++)
                #pragma unroll
                for (int j = 0; j < 4; j++)
                    if (r0 + i == c0 + j) s[i][j] = -1e30f;
        }

        // Row-max partials -> reduce by 64 threads
        #pragma unroll
        for (int i = 0; i < 4; i++) {
            const float pm = fmaxf(fmaxf(s[i][0], s[i][1]), fmaxf(s[i][2], s[i][3]));
            red[(r0 + i) * 17 + tx] = pm;
        }
        __syncthreads();
        if (tid < 64) {
            float mx = -1e30f;
            #pragma unroll
            for (int t = 0; t < 16; t++) mx = fmaxf(mx, red[tid * 17 + t]);
            const float mo = m_s[tid];
            const float mn = fmaxf(mo, mx);
            m_s[tid] = mn;
            a_s[tid] = __expf(mo - mn);
        }
        __syncthreads();

        // P = exp(S - m_new), store transposed into Ps (aliases Ks), rowsum
        float* Ps = Ks;
        float psum[4] = {0.f, 0.f, 0.f, 0.f};
        #pragma unroll
        for (int i = 0; i < 4; i++) {
            const float mn = m_s[r0 + i];
            #pragma unroll
            for (int j = 0; j < 4; j++) {
                const float p = __expf(s[i][j] - mn);
                psum[i] += p;
                Ps[(c0 + j) * QS_STRIDE + (r0 + i)] = p;
            }
        }
        #pragma unroll
        for (int i = 0; i < 4; i++) red[(r0 + i) * 17 + tx] = psum[i];
        __syncthreads();
        if (tid < 64) {
            float ss = 0.f;
            #pragma unroll
            for (int t = 0; t < 16; t++) ss += red[tid * 17 + t];
            l_s[tid] = l_s[tid] * a_s[tid] + ss;
        }

        // O = O*alpha + P @ V
        #pragma unroll
        for (int i = 0; i < 4; i++) {
            const float al = a_s[r0 + i];
            #pragma unroll
            for (int j = 0; j < 4; j++) o[i][j] *= al;
        }
        #pragma unroll 8
        for (int k = 0; k < 64; k++) {
            const float4 a = *reinterpret_cast<const float4*>(&Ps[k * QS_STRIDE + r0]);
            const float4 bv = *reinterpret_cast<const float4*>(&Vs[k * 64 + c0]);
            const float aa[4] = {a.x, a.y, a.z, a.w};
            const float bb[4] = {bv.x, bv.y, bv.z, bv.w};
            #pragma unroll
            for (int i = 0; i < 4; i++)
                #pragma unroll
                for (int j = 0; j < 4; j++) o[i][j] += aa[i] * bb[j];
        }
    }

    __syncthreads();   // l_s final
    #pragma unroll
    for (int i = 0; i < 4; i++) {
        const float inv = 1.f / l_s[r0 + i];
        const int l = l0q + r0 + i;
        #pragma unroll
        for (int j = 0; j < 4; j++) {
            g_attn[((size_t)(b * KL + l)) * KDIM + h * KD + c0 + j] = o[i][j] * inv;
        }
    }
}

// ---------------------------------------------------------------------------

extern "C" void kernel_launch(void* const* d_in, const int* in_sizes, int n_in,
                              void* d_out, int out_size)
{
    const float* x  = (const float*)d_in[0];
    const float* Wq = (const float*)d_in[1];
    const float* Wk = (const float*)d_in[2];
    const float* Wv = (const float*)d_in[3];
    const float* Wo = (const float*)d_in[4];
    float* out = (float*)d_out;

    const size_t attn_smem = (size_t)ATTN_SMEM_FLOATS * sizeof(float);
    cudaFuncSetAttribute(attn_kernel,
                         cudaFuncAttributeMaxDynamicSharedMemorySize,
                         (int)attn_smem);

    dim3 g_qkv(KDIM / 64, KM / 64, 3);
    qkv_gemm<<<g_qkv, 256>>>(x, Wq, Wk, Wv);

    attn_kernel<<<KB * KH * (KL / 64), 256, attn_smem>>>();

    dim3 g_out(KDIM / 64, KM / 64);
    out_gemm<<<g_out, 256>>>(Wo, out);
}

// round 4
// speedup vs baseline: 1.4546x; 1.4537x over previous
#include <cuda_runtime.h>
#include <cuda_bf16.h>
#include <cstdint>

// ---------------------------------------------------------------------------
// DiagonnalyMaskedSelfAttention: B=2, L=2048, DIM=1024, H=16, D=64, fp32.
// Round 4: projection GEMMs on mma.sync (bf16 hi/lo 3-term fp32 emulation;
// target is plain sm_100 so tcgen05 is unavailable). Flash-attention scalar.
// ---------------------------------------------------------------------------

#define KB   2
#define KL   2048
#define KDIM 1024
#define KH   16
#define KD   64
#define KM   (KB * KL)   // 4096 rows

// ---------------- device scratch (no allocations allowed) ------------------
__device__ __align__(16) float g_q[KB * KH * KL * KD];       // [b,h,l,d]
__device__ __align__(16) float g_k[KB * KH * KL * KD];
__device__ __align__(16) float g_v[KB * KH * KL * KD];
__device__ __align__(16) __nv_bfloat16 g_xh[KM * KDIM];      // x split hi/lo
__device__ __align__(16) __nv_bfloat16 g_xl[KM * KDIM];
__device__ __align__(16) __nv_bfloat16 g_wh[4][KDIM * KDIM]; // W^T [n][k] hi
__device__ __align__(16) __nv_bfloat16 g_wl[4][KDIM * KDIM]; // W^T [n][k] lo
__device__ __align__(16) __nv_bfloat16 g_ah[KM * KDIM];      // attn out hi/lo
__device__ __align__(16) __nv_bfloat16 g_al[KM * KDIM];

// ---------------- warp-mma helpers -----------------------------------------
__device__ __forceinline__ uint32_t smem_u32(const void* p) {
    uint32_t a;
    asm("{ .reg .u64 t; cvta.to.shared.u64 t, %1; cvt.u32.u64 %0, t; }"
        : "=r"(a) : "l"(p));
    return a;
}

__device__ __forceinline__ void ldmx4(uint32_t addr, uint32_t& r0, uint32_t& r1,
                                      uint32_t& r2, uint32_t& r3) {
    asm volatile("ldmatrix.sync.aligned.m8n8.x4.shared.b16 {%0,%1,%2,%3}, [%4];"
                 : "=r"(r0), "=r"(r1), "=r"(r2), "=r"(r3) : "r"(addr));
}

__device__ __forceinline__ void mma16816(float* c, uint32_t a0, uint32_t a1,
                                         uint32_t a2, uint32_t a3,
                                         uint32_t b0, uint32_t b1) {
    asm volatile(
        "mma.sync.aligned.m16n8k16.row.col.f32.bf16.bf16.f32 "
        "{%0,%1,%2,%3}, {%4,%5,%6,%7}, {%8,%9}, {%0,%1,%2,%3};"
        : "+f"(c[0]), "+f"(c[1]), "+f"(c[2]), "+f"(c[3])
        : "r"(a0), "r"(a1), "r"(a2), "r"(a3), "r"(b0), "r"(b1));
}

__device__ __forceinline__ uint32_t swz(uint32_t bo) {
    return bo ^ ((bo >> 3) & 0x70);
}

// ---------------------------------------------------------------------------
// Conversion kernels
// ---------------------------------------------------------------------------

// fp32 -> bf16 hi/lo split of x (float4 vectorized), writes g_xh/g_xl
__global__ __launch_bounds__(256) void split_kernel(const float* __restrict__ s)
{
    const int i = blockIdx.x * blockDim.x + threadIdx.x;   // n4 = KM*KDIM/4
    const float4 v = reinterpret_cast<const float4*>(s)[i];
    const float a[4] = {v.x, v.y, v.z, v.w};
    #pragma unroll
    for (int j = 0; j < 4; j++) {
        const __nv_bfloat16 hi = __float2bfloat16(a[j]);
        g_xh[i * 4 + j] = hi;
        g_xl[i * 4 + j] = __float2bfloat16(a[j] - __bfloat162float(hi));
    }
}

// W [k][n] fp32 -> B [n][k] bf16 hi/lo (tiled transpose)
__global__ __launch_bounds__(256) void wsplit_kernel(
    const float* __restrict__ W, int widx)
{
    __shared__ float t[32][33];
    const int k0 = blockIdx.y << 5;
    const int n0 = blockIdx.x << 5;
    const int tx = threadIdx.x;         // 0..31
    const int ty = threadIdx.y;         // 0..7
    #pragma unroll
    for (int i = 0; i < 4; i++)
        t[ty + i * 8][tx] = W[(size_t)(k0 + ty + i * 8) * KDIM + n0 + tx];
    __syncthreads();
    __nv_bfloat16* Bh = g_wh[widx];
    __nv_bfloat16* Bl = g_wl[widx];
    #pragma unroll
    for (int i = 0; i < 4; i++) {
        const float v = t[tx][ty + i * 8];
        const __nv_bfloat16 hi = __float2bfloat16(v);
        const size_t o = (size_t)(n0 + ty + i * 8) * KDIM + k0 + tx;
        Bh[o] = hi;
        Bl[o] = __float2bfloat16(v - __bfloat162float(hi));
    }
}

// ---------------------------------------------------------------------------
// Warp-MMA GEMM: D[128x128 tile] = A[128x1024] * B[128x1024]^T, 3-term bf16.
// mode 0: A = x split, B = g_w[z], out -> g_q/g_k/g_v in [b,h,l,d]
// mode 1: A = attn split, B = g_w[3], out -> dout row-major
// SMEM: Ah@0, Al@16K, Bh@32K, Bl@48K, each [128 rows][64 bf16] SW128-swizzled.
// ---------------------------------------------------------------------------

#define GEMM_SMEM 65536

__global__ __launch_bounds__(256, 2) void mma_gemm(int mode, float* __restrict__ dout)
{
    extern __shared__ __align__(128) char smem[];
    const uint32_t sb = smem_u32(smem);

    const int tid  = threadIdx.x;
    const int wid  = tid >> 5;
    const int lane = tid & 31;
    const int wm   = wid >> 2;          // 0..1  warp row (64 rows each)
    const int wn   = wid & 3;           // 0..3  warp col (32 cols each)

    const int M0 = blockIdx.y << 7;
    const int N0 = blockIdx.x << 7;
    const int z  = blockIdx.z;

    const __nv_bfloat16* Agh = (mode == 0) ? g_xh : g_ah;
    const __nv_bfloat16* Agl = (mode == 0) ? g_xl : g_al;
    const int widx = (mode == 0) ? z : 3;
    const __nv_bfloat16* Bgh = g_wh[widx];
    const __nv_bfloat16* Bgl = g_wl[widx];

    float acc[4][4][4];
    #pragma unroll
    for (int mt = 0; mt < 4; mt++)
        #pragma unroll
        for (int nt = 0; nt < 4; nt++)
            #pragma unroll
            for (int e = 0; e < 4; e++) acc[mt][nt][e] = 0.f;

    // precomputed lane pieces for ldmatrix addressing
    const int a_row_l = lane & 15;                 // A frag row offset
    const int a_col_l = (lane >> 4) << 3;          // A frag k offset (0/8)
    const int b_row_l = (lane & 7) + ((lane >> 4) << 3);  // B frag n offset
    const int b_col_l = ((lane >> 3) & 1) << 3;    // B frag k offset (0/8)

    for (int c = 0; c < 16; c++) {
        const int k0 = c << 6;
        __syncthreads();   // previous mma phase done before overwrite

        // gmem -> smem: 4 tiles of [128][64] bf16 with SW128 swizzle
        #pragma unroll
        for (int t = 0; t < 4; t++) {
            const int u  = tid + (t << 8);         // 0..1023 (16B units)
            const int r  = u >> 3;                 // row 0..127
            const int cu = u & 7;                  // 16B unit in row
            const uint32_t sw = swz((r << 7) + (cu << 4));
            const size_t aoff = (size_t)(M0 + r) * KDIM + k0 + (cu << 3);
            const size_t boff = (size_t)(N0 + r) * KDIM + k0 + (cu << 3);
            *reinterpret_cast<uint4*>(smem + sw) =
                *reinterpret_cast<const uint4*>(Agh + aoff);
            *reinterpret_cast<uint4*>(smem + 16384 + sw) =
                *reinterpret_cast<const uint4*>(Agl + aoff);
            *reinterpret_cast<uint4*>(smem + 32768 + sw) =
                *reinterpret_cast<const uint4*>(Bgh + boff);
            *reinterpret_cast<uint4*>(smem + 49152 + sw) =
                *reinterpret_cast<const uint4*>(Bgl + boff);
        }
        __syncthreads();

        #pragma unroll
        for (int ks = 0; ks < 4; ks++) {
            const int kb = ks << 4;   // bf16 k base within chunk

            // B fragments for all 4 n-tiles (hi & lo): 2+2 ldmatrix.x4
            uint32_t bh[4][2], bl[4][2];
            #pragma unroll
            for (int ntp = 0; ntp < 2; ntp++) {
                const int brow = wn * 32 + ntp * 16 + b_row_l;
                const uint32_t bo = (uint32_t)(brow << 7) + ((kb + b_col_l) << 1);
                const uint32_t sw = swz(bo);
                ldmx4(sb + 32768 + sw, bh[2 * ntp][0], bh[2 * ntp][1],
                      bh[2 * ntp + 1][0], bh[2 * ntp + 1][1]);
                ldmx4(sb + 49152 + sw, bl[2 * ntp][0], bl[2 * ntp][1],
                      bl[2 * ntp + 1][0], bl[2 * ntp + 1][1]);
            }

            #pragma unroll
            for (int mt = 0; mt < 4; mt++) {
                const int arow = wm * 64 + mt * 16 + a_row_l;
                const uint32_t bo = (uint32_t)(arow << 7) + ((kb + a_col_l) << 1);
                const uint32_t sw = swz(bo);
                uint32_t ah0, ah1, ah2, ah3, al0, al1, al2, al3;
                ldmx4(sb + sw,         ah0, ah1, ah2, ah3);
                ldmx4(sb + 16384 + sw, al0, al1, al2, al3);
                #pragma unroll
                for (int nt = 0; nt < 4; nt++) {
                    mma16816(acc[mt][nt], ah0, ah1, ah2, ah3, bh[nt][0], bh[nt][1]);
                    mma16816(acc[mt][nt], ah0, ah1, ah2, ah3, bl[nt][0], bl[nt][1]);
                    mma16816(acc[mt][nt], al0, al1, al2, al3, bh[nt][0], bh[nt][1]);
                }
            }
        }
    }

    // Epilogue: fragment -> gmem (float2 per pair)
    float* outp;
    if (mode == 0) outp = (z == 0) ? g_q : (z == 1 ? g_k : g_v);
    else           outp = dout;

    const int rl = lane >> 2;           // 0..7
    const int cl = (lane & 3) << 1;     // 0,2,4,6

    #pragma unroll
    for (int mt = 0; mt < 4; mt++) {
        #pragma unroll
        for (int nt = 0; nt < 4; nt++) {
            const int col = N0 + wn * 32 + nt * 8 + cl;
            #pragma unroll
            for (int half = 0; half < 2; half++) {
                const int row = M0 + wm * 64 + mt * 16 + rl + half * 8;
                const float2 v = make_float2(acc[mt][nt][half * 2],
                                             acc[mt][nt][half * 2 + 1]);
                if (mode == 0) {
                    const int b = row >> 11, l = row & 2047;
                    const int h = col >> 6,  d = col & 63;
                    *reinterpret_cast<float2*>(
                        outp + ((size_t)((b << 4) + h) * KL + l) * KD + d) = v;
                } else {
                    *reinterpret_cast<float2*>(outp + (size_t)row * KDIM + col) = v;
                }
            }
        }
    }
}

// ---------------------------------------------------------------------------
// Flash attention with diagonal self-mask (scalar fp32, known-good).
// Epilogue writes bf16 hi/lo for the tensor-core output projection.
// ---------------------------------------------------------------------------

#define QS_STRIDE 68
#define ATTN_SMEM_FLOATS (64 * 68 * 2 + 64 * 64 + 64 * 17 + 3 * 64)

__global__ __launch_bounds__(256) void attn_kernel()
{
    extern __shared__ float sm[];
    float* Qs  = sm;
    float* Ks  = Qs + 64 * QS_STRIDE;
    float* Vs  = Ks + 64 * QS_STRIDE;
    float* red = Vs + 64 * 64;
    float* m_s = red + 64 * 17;
    float* a_s = m_s + 64;
    float* l_s = a_s + 64;

    const int tid = threadIdx.x;
    const int tx  = tid & 15;
    const int ty  = tid >> 4;
    const int r0  = ty << 2;
    const int c0  = tx << 2;

    const int bid = blockIdx.x;
    const int qt  = bid & 31;
    const int bh  = bid >> 5;
    const int l0q = qt << 6;
    const int b   = bh >> 4;
    const int h   = bh & 15;

    const float* qptr = g_q + (size_t)bh * KL * KD;
    const float* kptr = g_k + (size_t)bh * KL * KD;
    const float* vptr = g_v + (size_t)bh * KL * KD;

    const float scale = 0.125f;

    #pragma unroll
    for (int p = 0; p < 4; p++) {
        const int idx = tid + (p << 8);
        const int row = idx >> 4;
        const int c4  = (idx & 15) << 2;
        const float4 v = *reinterpret_cast<const float4*>(
            qptr + (size_t)(l0q + row) * KD + c4);
        Qs[(c4 + 0) * QS_STRIDE + row] = v.x * scale;
        Qs[(c4 + 1) * QS_STRIDE + row] = v.y * scale;
        Qs[(c4 + 2) * QS_STRIDE + row] = v.z * scale;
        Qs[(c4 + 3) * QS_STRIDE + row] = v.w * scale;
    }
    if (tid < 64) { m_s[tid] = -1e30f; l_s[tid] = 0.f; }

    float o[4][4];
    #pragma unroll
    for (int i = 0; i < 4; i++)
        #pragma unroll
        for (int j = 0; j < 4; j++) o[i][j] = 0.f;

    for (int kt = 0; kt < 32; kt++) {
        const int l0k = kt << 6;
        __syncthreads();

        #pragma unroll
        for (int p = 0; p < 4; p++) {
            const int idx = tid + (p << 8);
            const int row = idx >> 4;
            const int c4  = (idx & 15) << 2;
            const float4 kv = *reinterpret_cast<const float4*>(
                kptr + (size_t)(l0k + row) * KD + c4);
            Ks[(c4 + 0) * QS_STRIDE + row] = kv.x;
            Ks[(c4 + 1) * QS_STRIDE + row] = kv.y;
            Ks[(c4 + 2) * QS_STRIDE + row] = kv.z;
            Ks[(c4 + 3) * QS_STRIDE + row] = kv.w;
            const float4 vv = *reinterpret_cast<const float4*>(
                vptr + (size_t)(l0k + row) * KD + c4);
            *reinterpret_cast<float4*>(&Vs[row * 64 + c4]) = vv;
        }
        __syncthreads();

        float s[4][4];
        #pragma unroll
        for (int i = 0; i < 4; i++)
            #pragma unroll
            for (int j = 0; j < 4; j++) s[i][j] = 0.f;

        #pragma unroll 8
        for (int d = 0; d < 64; d++) {
            const float4 a  = *reinterpret_cast<const float4*>(&Qs[d * QS_STRIDE + r0]);
            const float4 bq = *reinterpret_cast<const float4*>(&Ks[d * QS_STRIDE + c0]);
            const float aa[4] = {a.x, a.y, a.z, a.w};
            const float bb[4] = {bq.x, bq.y, bq.z, bq.w};
            #pragma unroll
            for (int i = 0; i < 4; i++)
                #pragma unroll
                for (int j = 0; j < 4; j++) s[i][j] += aa[i] * bb[j];
        }

        if (l0q == l0k) {
            #pragma unroll
            for (int i = 0; i < 4; i++)
                #pragma unroll
                for (int j = 0; j < 4; j++)
                    if (r0 + i == c0 + j) s[i][j] = -1e30f;
        }

        #pragma unroll
        for (int i = 0; i < 4; i++) {
            const float pm = fmaxf(fmaxf(s[i][0], s[i][1]), fmaxf(s[i][2], s[i][3]));
            red[(r0 + i) * 17 + tx] = pm;
        }
        __syncthreads();
        if (tid < 64) {
            float mx = -1e30f;
            #pragma unroll
            for (int t = 0; t < 16; t++) mx = fmaxf(mx, red[tid * 17 + t]);
            const float mo = m_s[tid];
            const float mn = fmaxf(mo, mx);
            m_s[tid] = mn;
            a_s[tid] = __expf(mo - mn);
        }
        __syncthreads();

        float* Ps = Ks;
        float psum[4] = {0.f, 0.f, 0.f, 0.f};
        #pragma unroll
        for (int i = 0; i < 4; i++) {
            const float mn = m_s[r0 + i];
            #pragma unroll
            for (int j = 0; j < 4; j++) {
                const float p = __expf(s[i][j] - mn);
                psum[i] += p;
                Ps[(c0 + j) * QS_STRIDE + (r0 + i)] = p;
            }
        }
        #pragma unroll
        for (int i = 0; i < 4; i++) red[(r0 + i) * 17 + tx] = psum[i];
        __syncthreads();
        if (tid < 64) {
            float ss = 0.f;
            #pragma unroll
            for (int t = 0; t < 16; t++) ss += red[tid * 17 + t];
            l_s[tid] = l_s[tid] * a_s[tid] + ss;
        }

        #pragma unroll
        for (int i = 0; i < 4; i++) {
            const float al = a_s[r0 + i];
            #pragma unroll
            for (int j = 0; j < 4; j++) o[i][j] *= al;
        }
        #pragma unroll 8
        for (int k = 0; k < 64; k++) {
            const float4 a  = *reinterpret_cast<const float4*>(&Ps[k * QS_STRIDE + r0]);
            const float4 bv = *reinterpret_cast<const float4*>(&Vs[k * 64 + c0]);
            const float aa[4] = {a.x, a.y, a.z, a.w};
            const float bb[4] = {bv.x, bv.y, bv.z, bv.w};
            #pragma unroll
            for (int i = 0; i < 4; i++)
                #pragma unroll
                for (int j = 0; j < 4; j++) o[i][j] += aa[i] * bb[j];
        }
    }

    __syncthreads();
    #pragma unroll
    for (int i = 0; i < 4; i++) {
        const float inv = 1.f / l_s[r0 + i];
        const int l = l0q + r0 + i;
        #pragma unroll
        for (int j = 0; j < 4; j++) {
            const size_t idx = ((size_t)(b * KL + l)) * KDIM + h * KD + c0 + j;
            const float val = o[i][j] * inv;
            const __nv_bfloat16 hi = __float2bfloat16(val);
            g_ah[idx] = hi;
            g_al[idx] = __float2bfloat16(val - __bfloat162float(hi));
        }
    }
}

// ---------------------------------------------------------------------------

extern "C" void kernel_launch(void* const* d_in, const int* in_sizes, int n_in,
                              void* d_out, int out_size)
{
    const float* x  = (const float*)d_in[0];
    const float* Wq = (const float*)d_in[1];
    const float* Wk = (const float*)d_in[2];
    const float* Wv = (const float*)d_in[3];
    const float* Wo = (const float*)d_in[4];
    float* out = (float*)d_out;

    const size_t attn_smem = (size_t)ATTN_SMEM_FLOATS * sizeof(float);
    cudaFuncSetAttribute(attn_kernel,
                         cudaFuncAttributeMaxDynamicSharedMemorySize,
                         (int)attn_smem);
    cudaFuncSetAttribute(mma_gemm,
                         cudaFuncAttributeMaxDynamicSharedMemorySize,
                         GEMM_SMEM);

    // 1. split x into bf16 hi/lo
    split_kernel<<<KM * KDIM / 4 / 256, 256>>>(x);

    // 2. transpose+split the 4 weights
    dim3 wgrid(KDIM / 32, KDIM / 32);
    dim3 wblk(32, 8);
    wsplit_kernel<<<wgrid, wblk>>>(Wq, 0);
    wsplit_kernel<<<wgrid, wblk>>>(Wk, 1);
    wsplit_kernel<<<wgrid, wblk>>>(Wv, 2);
    wsplit_kernel<<<wgrid, wblk>>>(Wo, 3);

    // 3. QKV projections on tensor cores (HMMA)
    dim3 g_qkv(KDIM / 128, KM / 128, 3);
    mma_gemm<<<g_qkv, 256, GEMM_SMEM>>>(0, nullptr);

    // 4. attention
    attn_kernel<<<KB * KH * (KL / 64), 256, attn_smem>>>();

    // 5. output projection on tensor cores
    dim3 g_out(KDIM / 128, KM / 128, 1);
    mma_gemm<<<g_out, 256, GEMM_SMEM>>>(1, out);
}

// round 6
// speedup vs baseline: 2.7658x; 1.9015x over previous
#include <cuda_runtime.h>
#include <cuda_bf16.h>
#include <cstdint>

// ---------------------------------------------------------------------------
// DiagonnalyMaskedSelfAttention: B=2, L=2048, DIM=1024, H=16, D=64, fp32.
// Round 6: everything on mma.sync bf16 hi/lo emulated-fp32.
// Fix vs R5: non-trans B-operand ldmatrix lane addressing (register order
// must be {n-lo/k-lo, n-lo/k-hi, n-hi/k-lo, n-hi/k-hi}).
// ---------------------------------------------------------------------------

#define KB   2
#define KL   2048
#define KDIM 1024
#define KH   16
#define KD   64
#define KM   (KB * KL)   // 4096 rows

// ---------------- device scratch (no allocations allowed) ------------------
__device__ __align__(16) __nv_bfloat16 g_xh[KM * KDIM];      // x split hi/lo
__device__ __align__(16) __nv_bfloat16 g_xl[KM * KDIM];
__device__ __align__(16) __nv_bfloat16 g_wh[4][KDIM * KDIM]; // W^T [n][k] hi
__device__ __align__(16) __nv_bfloat16 g_wl[4][KDIM * KDIM]; // W^T [n][k] lo
// q/k/v split hi/lo, layout [b*16+h][l][d]; q pre-scaled by 1/8
__device__ __align__(16) __nv_bfloat16 g_qh[KB * KH * KL * KD];
__device__ __align__(16) __nv_bfloat16 g_ql[KB * KH * KL * KD];
__device__ __align__(16) __nv_bfloat16 g_kh[KB * KH * KL * KD];
__device__ __align__(16) __nv_bfloat16 g_kl[KB * KH * KL * KD];
__device__ __align__(16) __nv_bfloat16 g_vh[KB * KH * KL * KD];
__device__ __align__(16) __nv_bfloat16 g_vl[KB * KH * KL * KD];
__device__ __align__(16) __nv_bfloat16 g_ah[KM * KDIM];      // attn out hi/lo
__device__ __align__(16) __nv_bfloat16 g_al[KM * KDIM];

// ---------------- helpers ---------------------------------------------------
__device__ __forceinline__ uint32_t smem_u32(const void* p) {
    uint32_t a;
    asm("{ .reg .u64 t; cvta.to.shared.u64 t, %1; cvt.u32.u64 %0, t; }"
        : "=r"(a) : "l"(p));
    return a;
}

__device__ __forceinline__ void ldmx4(uint32_t addr, uint32_t& r0, uint32_t& r1,
                                      uint32_t& r2, uint32_t& r3) {
    asm volatile("ldmatrix.sync.aligned.m8n8.x4.shared.b16 {%0,%1,%2,%3}, [%4];"
                 : "=r"(r0), "=r"(r1), "=r"(r2), "=r"(r3) : "r"(addr));
}

__device__ __forceinline__ void ldmx4t(uint32_t addr, uint32_t& r0, uint32_t& r1,
                                       uint32_t& r2, uint32_t& r3) {
    asm volatile("ldmatrix.sync.aligned.m8n8.x4.trans.shared.b16 {%0,%1,%2,%3}, [%4];"
                 : "=r"(r0), "=r"(r1), "=r"(r2), "=r"(r3) : "r"(addr));
}

__device__ __forceinline__ void mma16816(float* c, uint32_t a0, uint32_t a1,
                                         uint32_t a2, uint32_t a3,
                                         uint32_t b0, uint32_t b1) {
    asm volatile(
        "mma.sync.aligned.m16n8k16.row.col.f32.bf16.bf16.f32 "
        "{%0,%1,%2,%3}, {%4,%5,%6,%7}, {%8,%9}, {%0,%1,%2,%3};"
        : "+f"(c[0]), "+f"(c[1]), "+f"(c[2]), "+f"(c[3])
        : "r"(a0), "r"(a1), "r"(a2), "r"(a3), "r"(b0), "r"(b1));
}

__device__ __forceinline__ uint32_t swz(uint32_t bo) {
    return bo ^ ((bo >> 3) & 0x70);
}

// pack two floats into bf16x2 (first arg -> low 16 bits)
__device__ __forceinline__ uint32_t packbf(float lo, float hi) {
    uint32_t r;
    asm("cvt.rn.bf16x2.f32 %0, %1, %2;" : "=r"(r) : "f"(hi), "f"(lo));
    return r;
}

__device__ __forceinline__ float bfr(float v) {    // bf16-rounded value
    return __bfloat162float(__float2bfloat16(v));
}

// ---------------------------------------------------------------------------
// Conversion kernels
// ---------------------------------------------------------------------------

__global__ __launch_bounds__(256) void split_kernel(const float* __restrict__ s)
{
    const int i = blockIdx.x * blockDim.x + threadIdx.x;
    const float4 v = reinterpret_cast<const float4*>(s)[i];
    const float a[4] = {v.x, v.y, v.z, v.w};
    #pragma unroll
    for (int j = 0; j < 4; j++) {
        const __nv_bfloat16 hi = __float2bfloat16(a[j]);
        g_xh[i * 4 + j] = hi;
        g_xl[i * 4 + j] = __float2bfloat16(a[j] - __bfloat162float(hi));
    }
}

__global__ __launch_bounds__(256) void wsplit_kernel(
    const float* __restrict__ W, int widx)
{
    __shared__ float t[32][33];
    const int k0 = blockIdx.y << 5;
    const int n0 = blockIdx.x << 5;
    const int tx = threadIdx.x;
    const int ty = threadIdx.y;
    #pragma unroll
    for (int i = 0; i < 4; i++)
        t[ty + i * 8][tx] = W[(size_t)(k0 + ty + i * 8) * KDIM + n0 + tx];
    __syncthreads();
    __nv_bfloat16* Bh = g_wh[widx];
    __nv_bfloat16* Bl = g_wl[widx];
    #pragma unroll
    for (int i = 0; i < 4; i++) {
        const float v = t[tx][ty + i * 8];
        const __nv_bfloat16 hi = __float2bfloat16(v);
        const size_t o = (size_t)(n0 + ty + i * 8) * KDIM + k0 + tx;
        Bh[o] = hi;
        Bl[o] = __float2bfloat16(v - __bfloat162float(hi));
    }
}

// ---------------------------------------------------------------------------
// Warp-MMA GEMM: D[128x128 tile] = A[128x1024] * B[128x1024]^T, 3-term bf16.
// mode 0: A = x split, B = g_w[z]; out -> split bf16 q/k/v ([bh][l][d], q*1/8)
// mode 1: A = attn split, B = g_w[3]; out -> dout fp32 row-major
// ---------------------------------------------------------------------------

#define GEMM_SMEM 65536

__global__ __launch_bounds__(256, 2) void mma_gemm(int mode, float* __restrict__ dout)
{
    extern __shared__ __align__(128) char smem[];
    const uint32_t sb = smem_u32(smem);

    const int tid  = threadIdx.x;
    const int wid  = tid >> 5;
    const int lane = tid & 31;
    const int wm   = wid >> 2;
    const int wn   = wid & 3;

    const int M0 = blockIdx.y << 7;
    const int N0 = blockIdx.x << 7;
    const int z  = blockIdx.z;

    const __nv_bfloat16* Agh = (mode == 0) ? g_xh : g_ah;
    const __nv_bfloat16* Agl = (mode == 0) ? g_xl : g_al;
    const int widx = (mode == 0) ? z : 3;
    const __nv_bfloat16* Bgh = g_wh[widx];
    const __nv_bfloat16* Bgl = g_wl[widx];

    float acc[4][4][4];
    #pragma unroll
    for (int mt = 0; mt < 4; mt++)
        #pragma unroll
        for (int nt = 0; nt < 4; nt++)
            #pragma unroll
            for (int e = 0; e < 4; e++) acc[mt][nt][e] = 0.f;

    // A-fragment lane pattern (x4 regs = rowlo/klo, rowhi/klo, rowlo/khi, rowhi/khi)
    const int a_row_l = lane & 15;
    const int a_col_l = (lane >> 4) << 3;
    // B-fragment lane pattern (x4 regs = nlo/klo, nlo/khi, nhi/klo, nhi/khi)
    const int b_row_l = (lane & 7) + ((lane >> 4) << 3);
    const int b_col_l = ((lane >> 3) & 1) << 3;

    for (int c = 0; c < 16; c++) {
        const int k0 = c << 6;
        __syncthreads();

        #pragma unroll
        for (int t = 0; t < 4; t++) {
            const int u  = tid + (t << 8);
            const int r  = u >> 3;
            const int cu = u & 7;
            const uint32_t sw = swz((r << 7) + (cu << 4));
            const size_t aoff = (size_t)(M0 + r) * KDIM + k0 + (cu << 3);
            const size_t boff = (size_t)(N0 + r) * KDIM + k0 + (cu << 3);
            *reinterpret_cast<uint4*>(smem + sw) =
                *reinterpret_cast<const uint4*>(Agh + aoff);
            *reinterpret_cast<uint4*>(smem + 16384 + sw) =
                *reinterpret_cast<const uint4*>(Agl + aoff);
            *reinterpret_cast<uint4*>(smem + 32768 + sw) =
                *reinterpret_cast<const uint4*>(Bgh + boff);
            *reinterpret_cast<uint4*>(smem + 49152 + sw) =
                *reinterpret_cast<const uint4*>(Bgl + boff);
        }
        __syncthreads();

        #pragma unroll
        for (int ks = 0; ks < 4; ks++) {
            const int kb = ks << 4;

            uint32_t bhf[4][2], blf[4][2];
            #pragma unroll
            for (int ntp = 0; ntp < 2; ntp++) {
                const int brow = wn * 32 + ntp * 16 + b_row_l;
                const uint32_t sw = swz((uint32_t)(brow << 7) + ((kb + b_col_l) << 1));
                ldmx4(sb + 32768 + sw, bhf[2 * ntp][0], bhf[2 * ntp][1],
                      bhf[2 * ntp + 1][0], bhf[2 * ntp + 1][1]);
                ldmx4(sb + 49152 + sw, blf[2 * ntp][0], blf[2 * ntp][1],
                      blf[2 * ntp + 1][0], blf[2 * ntp + 1][1]);
            }

            #pragma unroll
            for (int mt = 0; mt < 4; mt++) {
                const int arow = wm * 64 + mt * 16 + a_row_l;
                const uint32_t sw = swz((uint32_t)(arow << 7) + ((kb + a_col_l) << 1));
                uint32_t ah0, ah1, ah2, ah3, al0, al1, al2, al3;
                ldmx4(sb + sw,         ah0, ah1, ah2, ah3);
                ldmx4(sb + 16384 + sw, al0, al1, al2, al3);
                #pragma unroll
                for (int nt = 0; nt < 4; nt++) {
                    mma16816(acc[mt][nt], ah0, ah1, ah2, ah3, bhf[nt][0], bhf[nt][1]);
                    mma16816(acc[mt][nt], ah0, ah1, ah2, ah3, blf[nt][0], blf[nt][1]);
                    mma16816(acc[mt][nt], al0, al1, al2, al3, bhf[nt][0], bhf[nt][1]);
                }
            }
        }
    }

    const int rl = lane >> 2;
    const int cl = (lane & 3) << 1;

    if (mode == 1) {
        #pragma unroll
        for (int mt = 0; mt < 4; mt++)
            #pragma unroll
            for (int nt = 0; nt < 4; nt++) {
                const int col = N0 + wn * 32 + nt * 8 + cl;
                #pragma unroll
                for (int half = 0; half < 2; half++) {
                    const int row = M0 + wm * 64 + mt * 16 + rl + half * 8;
                    *reinterpret_cast<float2*>(dout + (size_t)row * KDIM + col) =
                        make_float2(acc[mt][nt][half * 2], acc[mt][nt][half * 2 + 1]);
                }
            }
        return;
    }

    // mode 0: split into bf16 hi/lo q/k/v, [bh][l][d] layout; q scaled by 1/8
    const float qs = (z == 0) ? 0.125f : 1.0f;
    uint32_t* Oh = (uint32_t*)((z == 0) ? g_qh : (z == 1 ? g_kh : g_vh));
    uint32_t* Ol = (uint32_t*)((z == 0) ? g_ql : (z == 1 ? g_kl : g_vl));

    #pragma unroll
    for (int mt = 0; mt < 4; mt++)
        #pragma unroll
        for (int nt = 0; nt < 4; nt++) {
            const int col = N0 + wn * 32 + nt * 8 + cl;
            const int h = col >> 6, d = col & 63;
            #pragma unroll
            for (int half = 0; half < 2; half++) {
                const int row = M0 + wm * 64 + mt * 16 + rl + half * 8;
                const int b = row >> 11, l = row & 2047;
                const float v0 = acc[mt][nt][half * 2] * qs;
                const float v1 = acc[mt][nt][half * 2 + 1] * qs;
                const float h0 = bfr(v0), h1 = bfr(v1);
                const size_t off = (((size_t)((b << 4) + h) << 11) + l) * 64 + d;
                Oh[off >> 1] = packbf(h0, h1);
                Ol[off >> 1] = packbf(v0 - h0, v1 - h1);
            }
        }
}

// ---------------------------------------------------------------------------
// Flash attention on mma.sync. CTA = 128 queries of one (b,h); 8 warps each
// own 16 query rows (softmax fully warp-local). KV tiles of 64 keys.
// S = Qh*Kh + Qh*Kl + Ql*Kh ; O += Ph*Vh + Pl*Vh + Ph*Vl (both 3-term).
// SMEM 64KB: Qh@0 Ql@16K (128x64), Kh@32K Kl@40K Vh@48K Vl@56K (64x64 each).
// ---------------------------------------------------------------------------

#define ATTN_SMEM 65536

__global__ __launch_bounds__(256) void attn_mma()
{
    extern __shared__ __align__(128) char smem[];
    const uint32_t sb = smem_u32(smem);

    const int tid  = threadIdx.x;
    const int wid  = tid >> 5;
    const int lane = tid & 31;

    const int qt = blockIdx.x;
    const int bh = blockIdx.y;
    const int qb = qt << 7;

    const __nv_bfloat16* qh = g_qh + ((size_t)bh << 11) * KD;
    const __nv_bfloat16* ql = g_ql + ((size_t)bh << 11) * KD;
    const __nv_bfloat16* kh = g_kh + ((size_t)bh << 11) * KD;
    const __nv_bfloat16* kl = g_kl + ((size_t)bh << 11) * KD;
    const __nv_bfloat16* vh = g_vh + ((size_t)bh << 11) * KD;
    const __nv_bfloat16* vl = g_vl + ((size_t)bh << 11) * KD;

    // ---- load Q tile (hi/lo) into SMEM ----
    #pragma unroll
    for (int t = 0; t < 4; t++) {
        const int u  = tid + (t << 8);     // 0..1023
        const int r  = u >> 3;
        const int cu = u & 7;
        const uint32_t sw = swz((r << 7) + (cu << 4));
        const size_t go = (size_t)(qb + r) * KD + (cu << 3);
        *reinterpret_cast<uint4*>(smem + sw) =
            *reinterpret_cast<const uint4*>(qh + go);
        *reinterpret_cast<uint4*>(smem + 16384 + sw) =
            *reinterpret_cast<const uint4*>(ql + go);
    }
    __syncthreads();

    // ---- Q fragments resident in registers (A pattern) ----
    uint32_t aqh[4][4], aql[4][4];
    {
        const int arow = (wid << 4) + (lane & 15);
        #pragma unroll
        for (int kg = 0; kg < 4; kg++) {
            const uint32_t sw = swz((uint32_t)(arow << 7) +
                                    (((kg << 4) + ((lane >> 4) << 3)) << 1));
            ldmx4(sb + sw,         aqh[kg][0], aqh[kg][1], aqh[kg][2], aqh[kg][3]);
            ldmx4(sb + 16384 + sw, aql[kg][0], aql[kg][1], aql[kg][2], aql[kg][3]);
        }
    }

    float m0 = -1e30f, m1 = -1e30f, l0 = 0.f, l1 = 0.f;
    float o[8][4];
    #pragma unroll
    for (int nt = 0; nt < 8; nt++)
        #pragma unroll
        for (int e = 0; e < 4; e++) o[nt][e] = 0.f;

    // B-fragment lane pattern pieces for the K loads
    const int b_row_l = (lane & 7) + ((lane >> 4) << 3);
    const int b_col_l = ((lane >> 3) & 1) << 3;

    for (int kt = 0; kt < 32; kt++) {
        const int kb = kt << 6;
        __syncthreads();
        // ---- load K/V tiles (hi/lo) ----
        #pragma unroll
        for (int t = 0; t < 2; t++) {
            const int u  = tid + (t << 8);  // 0..511
            const int r  = u >> 3;
            const int cu = u & 7;
            const uint32_t sw = swz((r << 7) + (cu << 4));
            const size_t go = (size_t)(kb + r) * KD + (cu << 3);
            *reinterpret_cast<uint4*>(smem + 32768 + sw) =
                *reinterpret_cast<const uint4*>(kh + go);
            *reinterpret_cast<uint4*>(smem + 40960 + sw) =
                *reinterpret_cast<const uint4*>(kl + go);
            *reinterpret_cast<uint4*>(smem + 49152 + sw) =
                *reinterpret_cast<const uint4*>(vh + go);
            *reinterpret_cast<uint4*>(smem + 57344 + sw) =
                *reinterpret_cast<const uint4*>(vl + go);
        }
        __syncthreads();

        // ---- S = Q K^T (3-term) ----
        float s[8][4];
        #pragma unroll
        for (int nt = 0; nt < 8; nt++)
            #pragma unroll
            for (int e = 0; e < 4; e++) s[nt][e] = 0.f;

        #pragma unroll
        for (int kg = 0; kg < 4; kg++) {
            uint32_t kbh[8][2], kbl[8][2];
            #pragma unroll
            for (int ntp = 0; ntp < 4; ntp++) {
                const int krow = (ntp << 4) + b_row_l;          // key index
                const uint32_t sw = swz((uint32_t)(krow << 7) +
                                        (((kg << 4) + b_col_l) << 1));
                ldmx4(sb + 32768 + sw, kbh[2 * ntp][0], kbh[2 * ntp][1],
                      kbh[2 * ntp + 1][0], kbh[2 * ntp + 1][1]);
                ldmx4(sb + 40960 + sw, kbl[2 * ntp][0], kbl[2 * ntp][1],
                      kbl[2 * ntp + 1][0], kbl[2 * ntp + 1][1]);
            }
            #pragma unroll
            for (int nt = 0; nt < 8; nt++) {
                mma16816(s[nt], aqh[kg][0], aqh[kg][1], aqh[kg][2], aqh[kg][3],
                         kbh[nt][0], kbh[nt][1]);
                mma16816(s[nt], aqh[kg][0], aqh[kg][1], aqh[kg][2], aqh[kg][3],
                         kbl[nt][0], kbl[nt][1]);
                mma16816(s[nt], aql[kg][0], aql[kg][1], aql[kg][2], aql[kg][3],
                         kbh[nt][0], kbh[nt][1]);
            }
        }

        // ---- diagonal self-mask (only 2 tiles per q-tile can hit) ----
        if ((kt >> 1) == qt) {
            const int rg = qb + (wid << 4) + (lane >> 2);
            #pragma unroll
            for (int nt = 0; nt < 8; nt++) {
                const int cg = kb + (nt << 3) + ((lane & 3) << 1);
                if (rg == cg)         s[nt][0] = -1e30f;
                if (rg == cg + 1)     s[nt][1] = -1e30f;
                if (rg + 8 == cg)     s[nt][2] = -1e30f;
                if (rg + 8 == cg + 1) s[nt][3] = -1e30f;
            }
        }

        // ---- online softmax (warp-local, quad reductions) ----
        float mt0 = -1e30f, mt1 = -1e30f;
        #pragma unroll
        for (int nt = 0; nt < 8; nt++) {
            mt0 = fmaxf(mt0, fmaxf(s[nt][0], s[nt][1]));
            mt1 = fmaxf(mt1, fmaxf(s[nt][2], s[nt][3]));
        }
        mt0 = fmaxf(mt0, __shfl_xor_sync(0xffffffffu, mt0, 1));
        mt0 = fmaxf(mt0, __shfl_xor_sync(0xffffffffu, mt0, 2));
        mt1 = fmaxf(mt1, __shfl_xor_sync(0xffffffffu, mt1, 1));
        mt1 = fmaxf(mt1, __shfl_xor_sync(0xffffffffu, mt1, 2));

        const float mn0 = fmaxf(m0, mt0);
        const float mn1 = fmaxf(m1, mt1);
        const float al0 = __expf(m0 - mn0);
        const float al1 = __expf(m1 - mn1);
        m0 = mn0; m1 = mn1;

        float ps0 = 0.f, ps1 = 0.f;
        uint32_t ph[4][4], pl[4][4];
        #pragma unroll
        for (int nt = 0; nt < 8; nt++) {
            const float p0 = __expf(s[nt][0] - mn0);
            const float p1 = __expf(s[nt][1] - mn0);
            const float p2 = __expf(s[nt][2] - mn1);
            const float p3 = __expf(s[nt][3] - mn1);
            ps0 += p0 + p1;
            ps1 += p2 + p3;
            const float h0 = bfr(p0), h1 = bfr(p1), h2 = bfr(p2), h3 = bfr(p3);
            const int kg  = nt >> 1;
            const int ix  = (nt & 1) << 1;
            ph[kg][ix]     = packbf(h0, h1);
            ph[kg][ix + 1] = packbf(h2, h3);
            pl[kg][ix]     = packbf(p0 - h0, p1 - h1);
            pl[kg][ix + 1] = packbf(p2 - h2, p3 - h3);
        }
        ps0 += __shfl_xor_sync(0xffffffffu, ps0, 1);
        ps0 += __shfl_xor_sync(0xffffffffu, ps0, 2);
        ps1 += __shfl_xor_sync(0xffffffffu, ps1, 1);
        ps1 += __shfl_xor_sync(0xffffffffu, ps1, 2);
        l0 = l0 * al0 + ps0;
        l1 = l1 * al1 + ps1;

        #pragma unroll
        for (int nt = 0; nt < 8; nt++) {
            o[nt][0] *= al0;
            o[nt][1] *= al0;
            o[nt][2] *= al1;
            o[nt][3] *= al1;
        }

        // ---- O += P V (3-term); trans-loaded V fragments: k splits regs ----
        #pragma unroll
        for (int kg = 0; kg < 4; kg++) {
            uint32_t vbh[8][2], vbl[8][2];
            #pragma unroll
            for (int ntp = 0; ntp < 4; ntp++) {
                const uint32_t sw = swz(
                    (uint32_t)((((kg << 4) + (lane & 15)) << 7)) +
                    (((ntp << 4) + ((lane >> 4) << 3)) << 1));
                ldmx4t(sb + 49152 + sw, vbh[2 * ntp][0], vbh[2 * ntp][1],
                       vbh[2 * ntp + 1][0], vbh[2 * ntp + 1][1]);
                ldmx4t(sb + 57344 + sw, vbl[2 * ntp][0], vbl[2 * ntp][1],
                       vbl[2 * ntp + 1][0], vbl[2 * ntp + 1][1]);
            }
            #pragma unroll
            for (int nt = 0; nt < 8; nt++) {
                mma16816(o[nt], ph[kg][0], ph[kg][1], ph[kg][2], ph[kg][3],
                         vbh[nt][0], vbh[nt][1]);
                mma16816(o[nt], pl[kg][0], pl[kg][1], pl[kg][2], pl[kg][3],
                         vbh[nt][0], vbh[nt][1]);
                mma16816(o[nt], ph[kg][0], ph[kg][1], ph[kg][2], ph[kg][3],
                         vbl[nt][0], vbl[nt][1]);
            }
        }
    }

    // ---- epilogue: normalize, split hi/lo, write [b*l][h*d] ----
    const float inv0 = 1.f / l0;
    const float inv1 = 1.f / l1;
    const int b_ = bh >> 4, h_ = bh & 15;
    const int rg0 = qb + (wid << 4) + (lane >> 2);
    uint32_t* Ah = (uint32_t*)g_ah;
    uint32_t* Al = (uint32_t*)g_al;

    #pragma unroll
    for (int nt = 0; nt < 8; nt++) {
        const int d = (nt << 3) + ((lane & 3) << 1);
        const size_t o0 = ((size_t)(b_ << 11) + rg0) * KDIM + (h_ << 6) + d;
        const size_t o1 = o0 + (size_t)8 * KDIM;
        const float w0 = o[nt][0] * inv0, w1 = o[nt][1] * inv0;
        const float w2 = o[nt][2] * inv1, w3 = o[nt][3] * inv1;
        const float h0 = bfr(w0), h1 = bfr(w1), h2 = bfr(w2), h3 = bfr(w3);
        Ah[o0 >> 1] = packbf(h0, h1);
        Al[o0 >> 1] = packbf(w0 - h0, w1 - h1);
        Ah[o1 >> 1] = packbf(h2, h3);
        Al[o1 >> 1] = packbf(w2 - h2, w3 - h3);
    }
}

// ---------------------------------------------------------------------------

extern "C" void kernel_launch(void* const* d_in, const int* in_sizes, int n_in,
                              void* d_out, int out_size)
{
    const float* x  = (const float*)d_in[0];
    const float* Wq = (const float*)d_in[1];
    const float* Wk = (const float*)d_in[2];
    const float* Wv = (const float*)d_in[3];
    const float* Wo = (const float*)d_in[4];
    float* out = (float*)d_out;

    cudaFuncSetAttribute(mma_gemm,
                         cudaFuncAttributeMaxDynamicSharedMemorySize, GEMM_SMEM);
    cudaFuncSetAttribute(attn_mma,
                         cudaFuncAttributeMaxDynamicSharedMemorySize, ATTN_SMEM);

    // 1. split x into bf16 hi/lo
    split_kernel<<<KM * KDIM / 4 / 256, 256>>>(x);

    // 2. transpose+split the 4 weights
    dim3 wgrid(KDIM / 32, KDIM / 32);
    dim3 wblk(32, 8);
    wsplit_kernel<<<wgrid, wblk>>>(Wq, 0);
    wsplit_kernel<<<wgrid, wblk>>>(Wk, 1);
    wsplit_kernel<<<wgrid, wblk>>>(Wv, 2);
    wsplit_kernel<<<wgrid, wblk>>>(Wo, 3);

    // 3. QKV projections -> split bf16 q/k/v
    dim3 g_qkv(KDIM / 128, KM / 128, 3);
    mma_gemm<<<g_qkv, 256, GEMM_SMEM>>>(0, nullptr);

    // 4. flash attention on tensor cores
    dim3 g_attn(KL / 128, KB * KH);
    attn_mma<<<g_attn, 256, ATTN_SMEM>>>();

    // 5. output projection
    dim3 g_out(KDIM / 128, KM / 128, 1);
    mma_gemm<<<g_out, 256, GEMM_SMEM>>>(1, out);
}

// round 7
// speedup vs baseline: 3.0138x; 1.0896x over previous
#include <cuda_runtime.h>
#include <cuda_bf16.h>
#include <cstdint>

// ---------------------------------------------------------------------------
// DiagonnalyMaskedSelfAttention: B=2, L=2048, DIM=1024, H=16, D=64, fp32.
// Round 7: R6 (all-mma.sync, bf16 hi/lo 3-term emulated fp32) + 2-stage
// cp.async pipelines in both mma_gemm and attn_mma; fused weight-split.
// ---------------------------------------------------------------------------

#define KB   2
#define KL   2048
#define KDIM 1024
#define KH   16
#define KD   64
#define KM   (KB * KL)   // 4096 rows

// ---------------- device scratch (no allocations allowed) ------------------
__device__ __align__(16) __nv_bfloat16 g_xh[KM * KDIM];      // x split hi/lo
__device__ __align__(16) __nv_bfloat16 g_xl[KM * KDIM];
__device__ __align__(16) __nv_bfloat16 g_wh[4][KDIM * KDIM]; // W^T [n][k] hi
__device__ __align__(16) __nv_bfloat16 g_wl[4][KDIM * KDIM]; // W^T [n][k] lo
// q/k/v split hi/lo, layout [b*16+h][l][d]; q pre-scaled by 1/8
__device__ __align__(16) __nv_bfloat16 g_qh[KB * KH * KL * KD];
__device__ __align__(16) __nv_bfloat16 g_ql[KB * KH * KL * KD];
__device__ __align__(16) __nv_bfloat16 g_kh[KB * KH * KL * KD];
__device__ __align__(16) __nv_bfloat16 g_kl[KB * KH * KL * KD];
__device__ __align__(16) __nv_bfloat16 g_vh[KB * KH * KL * KD];
__device__ __align__(16) __nv_bfloat16 g_vl[KB * KH * KL * KD];
__device__ __align__(16) __nv_bfloat16 g_ah[KM * KDIM];      // attn out hi/lo
__device__ __align__(16) __nv_bfloat16 g_al[KM * KDIM];

// ---------------- helpers ---------------------------------------------------
__device__ __forceinline__ uint32_t smem_u32(const void* p) {
    uint32_t a;
    asm("{ .reg .u64 t; cvta.to.shared.u64 t, %1; cvt.u32.u64 %0, t; }"
        : "=r"(a) : "l"(p));
    return a;
}

__device__ __forceinline__ void ldmx4(uint32_t addr, uint32_t& r0, uint32_t& r1,
                                      uint32_t& r2, uint32_t& r3) {
    asm volatile("ldmatrix.sync.aligned.m8n8.x4.shared.b16 {%0,%1,%2,%3}, [%4];"
                 : "=r"(r0), "=r"(r1), "=r"(r2), "=r"(r3) : "r"(addr));
}

__device__ __forceinline__ void ldmx4t(uint32_t addr, uint32_t& r0, uint32_t& r1,
                                       uint32_t& r2, uint32_t& r3) {
    asm volatile("ldmatrix.sync.aligned.m8n8.x4.trans.shared.b16 {%0,%1,%2,%3}, [%4];"
                 : "=r"(r0), "=r"(r1), "=r"(r2), "=r"(r3) : "r"(addr));
}

__device__ __forceinline__ void mma16816(float* c, uint32_t a0, uint32_t a1,
                                         uint32_t a2, uint32_t a3,
                                         uint32_t b0, uint32_t b1) {
    asm volatile(
        "mma.sync.aligned.m16n8k16.row.col.f32.bf16.bf16.f32 "
        "{%0,%1,%2,%3}, {%4,%5,%6,%7}, {%8,%9}, {%0,%1,%2,%3};"
        : "+f"(c[0]), "+f"(c[1]), "+f"(c[2]), "+f"(c[3])
        : "r"(a0), "r"(a1), "r"(a2), "r"(a3), "r"(b0), "r"(b1));
}

__device__ __forceinline__ uint32_t swz(uint32_t bo) {
    return bo ^ ((bo >> 3) & 0x70);
}

__device__ __forceinline__ uint32_t packbf(float lo, float hi) {
    uint32_t r;
    asm("cvt.rn.bf16x2.f32 %0, %1, %2;" : "=r"(r) : "f"(hi), "f"(lo));
    return r;
}

__device__ __forceinline__ float bfr(float v) {
    return __bfloat162float(__float2bfloat16(v));
}

// cp.async (LDGSTS) 16B copy + group ops
__device__ __forceinline__ void cp16(uint32_t saddr, const void* gptr) {
    asm volatile("cp.async.cg.shared.global [%0], [%1], 16;"
                 :: "r"(saddr), "l"(gptr));
}
#define CP_COMMIT()  asm volatile("cp.async.commit_group;" ::: "memory")
#define CP_WAIT1()   asm volatile("cp.async.wait_group 1;"  ::: "memory")
#define CP_WAIT0()   asm volatile("cp.async.wait_group 0;"  ::: "memory")

// ---------------------------------------------------------------------------
// Conversion kernels
// ---------------------------------------------------------------------------

__global__ __launch_bounds__(256) void split_kernel(const float* __restrict__ s)
{
    const int i = blockIdx.x * blockDim.x + threadIdx.x;
    const float4 v = reinterpret_cast<const float4*>(s)[i];
    const float a[4] = {v.x, v.y, v.z, v.w};
    #pragma unroll
    for (int j = 0; j < 4; j++) {
        const __nv_bfloat16 hi = __float2bfloat16(a[j]);
        g_xh[i * 4 + j] = hi;
        g_xl[i * 4 + j] = __float2bfloat16(a[j] - __bfloat162float(hi));
    }
}

// all 4 weights transposed+split in one launch (blockIdx.z = which W)
__global__ __launch_bounds__(256) void wsplit_kernel(
    const float* __restrict__ W0, const float* __restrict__ W1,
    const float* __restrict__ W2, const float* __restrict__ W3)
{
    __shared__ float t[32][33];
    const int widx = blockIdx.z;
    const float* W = (widx == 0) ? W0 : (widx == 1 ? W1 : (widx == 2 ? W2 : W3));
    const int k0 = blockIdx.y << 5;
    const int n0 = blockIdx.x << 5;
    const int tx = threadIdx.x;
    const int ty = threadIdx.y;
    #pragma unroll
    for (int i = 0; i < 4; i++)
        t[ty + i * 8][tx] = W[(size_t)(k0 + ty + i * 8) * KDIM + n0 + tx];
    __syncthreads();
    __nv_bfloat16* Bh = g_wh[widx];
    __nv_bfloat16* Bl = g_wl[widx];
    #pragma unroll
    for (int i = 0; i < 4; i++) {
        const float v = t[tx][ty + i * 8];
        const __nv_bfloat16 hi = __float2bfloat16(v);
        const size_t o = (size_t)(n0 + ty + i * 8) * KDIM + k0 + tx;
        Bh[o] = hi;
        Bl[o] = __float2bfloat16(v - __bfloat162float(hi));
    }
}

// ---------------------------------------------------------------------------
// Warp-MMA GEMM with 2-stage cp.async pipeline.
// D[128x128 tile] = A[128x1024] * B[128x1024]^T, 3-term bf16 hi/lo.
// mode 0: A = x split, B = g_w[z]; out -> split bf16 q/k/v ([bh][l][d], q*1/8)
// mode 1: A = attn split, B = g_w[3]; out -> dout fp32 row-major
// SMEM: 2 stages x 64KB; per stage: Ah@0 Al@16K Bh@32K Bl@48K (128x64 SW128).
// ---------------------------------------------------------------------------

#define GEMM_SMEM 131072

__global__ __launch_bounds__(256) void mma_gemm(int mode, float* __restrict__ dout)
{
    extern __shared__ __align__(128) char smem[];
    const uint32_t sb = smem_u32(smem);

    const int tid  = threadIdx.x;
    const int wid  = tid >> 5;
    const int lane = tid & 31;
    const int wm   = wid >> 2;
    const int wn   = wid & 3;

    const int M0 = blockIdx.y << 7;
    const int N0 = blockIdx.x << 7;
    const int z  = blockIdx.z;

    const __nv_bfloat16* Agh = (mode == 0) ? g_xh : g_ah;
    const __nv_bfloat16* Agl = (mode == 0) ? g_xl : g_al;
    const int widx = (mode == 0) ? z : 3;
    const __nv_bfloat16* Bgh = g_wh[widx];
    const __nv_bfloat16* Bgl = g_wl[widx];

    float acc[4][4][4];
    #pragma unroll
    for (int mt = 0; mt < 4; mt++)
        #pragma unroll
        for (int nt = 0; nt < 4; nt++)
            #pragma unroll
            for (int e = 0; e < 4; e++) acc[mt][nt][e] = 0.f;

    const int a_row_l = lane & 15;
    const int a_col_l = (lane >> 4) << 3;
    const int b_row_l = (lane & 7) + ((lane >> 4) << 3);
    const int b_col_l = ((lane >> 3) & 1) << 3;

    // per-thread fixed pieces of the stage-load pattern
    // (4 rows x 16B each, same swizzled offsets for all 4 arrays)
    uint32_t ld_sw[4];
    size_t   ld_ao[4], ld_bo[4];
    #pragma unroll
    for (int t = 0; t < 4; t++) {
        const int u  = tid + (t << 8);
        const int r  = u >> 3;
        const int cu = u & 7;
        ld_sw[t] = swz((r << 7) + (cu << 4));
        ld_ao[t] = (size_t)(M0 + r) * KDIM + (cu << 3);
        ld_bo[t] = (size_t)(N0 + r) * KDIM + (cu << 3);
    }

    auto load_chunk = [&](int c, int stg) {
        const int k0 = c << 6;
        const uint32_t so = sb + ((uint32_t)stg << 16);
        #pragma unroll
        for (int t = 0; t < 4; t++) {
            cp16(so + ld_sw[t],         Agh + ld_ao[t] + k0);
            cp16(so + 16384 + ld_sw[t], Agl + ld_ao[t] + k0);
            cp16(so + 32768 + ld_sw[t], Bgh + ld_bo[t] + k0);
            cp16(so + 49152 + ld_sw[t], Bgl + ld_bo[t] + k0);
        }
        CP_COMMIT();
    };

    load_chunk(0, 0);

    for (int c = 0; c < 16; c++) {
        if (c + 1 < 16) { load_chunk(c + 1, (c + 1) & 1); CP_WAIT1(); }
        else            { CP_WAIT0(); }
        __syncthreads();

        const uint32_t stb = sb + ((uint32_t)(c & 1) << 16);

        #pragma unroll
        for (int ks = 0; ks < 4; ks++) {
            const int kb = ks << 4;

            uint32_t bhf[4][2], blf[4][2];
            #pragma unroll
            for (int ntp = 0; ntp < 2; ntp++) {
                const int brow = wn * 32 + ntp * 16 + b_row_l;
                const uint32_t sw = swz((uint32_t)(brow << 7) + ((kb + b_col_l) << 1));
                ldmx4(stb + 32768 + sw, bhf[2 * ntp][0], bhf[2 * ntp][1],
                      bhf[2 * ntp + 1][0], bhf[2 * ntp + 1][1]);
                ldmx4(stb + 49152 + sw, blf[2 * ntp][0], blf[2 * ntp][1],
                      blf[2 * ntp + 1][0], blf[2 * ntp + 1][1]);
            }

            #pragma unroll
            for (int mt = 0; mt < 4; mt++) {
                const int arow = wm * 64 + mt * 16 + a_row_l;
                const uint32_t sw = swz((uint32_t)(arow << 7) + ((kb + a_col_l) << 1));
                uint32_t ah0, ah1, ah2, ah3, al0, al1, al2, al3;
                ldmx4(stb + sw,         ah0, ah1, ah2, ah3);
                ldmx4(stb + 16384 + sw, al0, al1, al2, al3);
                #pragma unroll
                for (int nt = 0; nt < 4; nt++) {
                    mma16816(acc[mt][nt], ah0, ah1, ah2, ah3, bhf[nt][0], bhf[nt][1]);
                    mma16816(acc[mt][nt], ah0, ah1, ah2, ah3, blf[nt][0], blf[nt][1]);
                    mma16816(acc[mt][nt], al0, al1, al2, al3, bhf[nt][0], bhf[nt][1]);
                }
            }
        }
        __syncthreads();   // protect this stage from iter c+1's prefetch
    }

    const int rl = lane >> 2;
    const int cl = (lane & 3) << 1;

    if (mode == 1) {
        #pragma unroll
        for (int mt = 0; mt < 4; mt++)
            #pragma unroll
            for (int nt = 0; nt < 4; nt++) {
                const int col = N0 + wn * 32 + nt * 8 + cl;
                #pragma unroll
                for (int half = 0; half < 2; half++) {
                    const int row = M0 + wm * 64 + mt * 16 + rl + half * 8;
                    *reinterpret_cast<float2*>(dout + (size_t)row * KDIM + col) =
                        make_float2(acc[mt][nt][half * 2], acc[mt][nt][half * 2 + 1]);
                }
            }
        return;
    }

    // mode 0: split into bf16 hi/lo q/k/v, [bh][l][d] layout; q scaled by 1/8
    const float qs = (z == 0) ? 0.125f : 1.0f;
    uint32_t* Oh = (uint32_t*)((z == 0) ? g_qh : (z == 1 ? g_kh : g_vh));
    uint32_t* Ol = (uint32_t*)((z == 0) ? g_ql : (z == 1 ? g_kl : g_vl));

    #pragma unroll
    for (int mt = 0; mt < 4; mt++)
        #pragma unroll
        for (int nt = 0; nt < 4; nt++) {
            const int col = N0 + wn * 32 + nt * 8 + cl;
            const int h = col >> 6, d = col & 63;
            #pragma unroll
            for (int half = 0; half < 2; half++) {
                const int row = M0 + wm * 64 + mt * 16 + rl + half * 8;
                const int b = row >> 11, l = row & 2047;
                const float v0 = acc[mt][nt][half * 2] * qs;
                const float v1 = acc[mt][nt][half * 2 + 1] * qs;
                const float h0 = bfr(v0), h1 = bfr(v1);
                const size_t off = (((size_t)((b << 4) + h) << 11) + l) * 64 + d;
                Oh[off >> 1] = packbf(h0, h1);
                Ol[off >> 1] = packbf(v0 - h0, v1 - h1);
            }
        }
}

// ---------------------------------------------------------------------------
// Flash attention on mma.sync with 2-stage cp.async KV pipeline.
// CTA = 128 queries of one (b,h); 8 warps each own 16 query rows.
// S = Qh*Kh + Qh*Kl + Ql*Kh ; O += Ph*Vh + Pl*Vh + Ph*Vl.
// SMEM 96KB: Qh@0 Ql@16K (resident); KV stages @32K + s*32K:
//            kh@+0 kl@+8K vh@+16K vl@+24K (64x64 each, SW128).
// ---------------------------------------------------------------------------

#define ATTN_SMEM 98304

__global__ __launch_bounds__(256) void attn_mma()
{
    extern __shared__ __align__(128) char smem[];
    const uint32_t sb = smem_u32(smem);

    const int tid  = threadIdx.x;
    const int wid  = tid >> 5;
    const int lane = tid & 31;

    const int qt = blockIdx.x;
    const int bh = blockIdx.y;
    const int qb = qt << 7;

    const __nv_bfloat16* qh = g_qh + ((size_t)bh << 11) * KD;
    const __nv_bfloat16* ql = g_ql + ((size_t)bh << 11) * KD;
    const __nv_bfloat16* kh = g_kh + ((size_t)bh << 11) * KD;
    const __nv_bfloat16* kl = g_kl + ((size_t)bh << 11) * KD;
    const __nv_bfloat16* vh = g_vh + ((size_t)bh << 11) * KD;
    const __nv_bfloat16* vl = g_vl + ((size_t)bh << 11) * KD;

    // per-thread fixed pieces of the KV stage-load pattern (2 rows x 16B)
    uint32_t kv_sw[2];
    size_t   kv_go[2];
    #pragma unroll
    for (int t = 0; t < 2; t++) {
        const int u  = tid + (t << 8);
        const int r  = u >> 3;
        const int cu = u & 7;
        kv_sw[t] = swz((r << 7) + (cu << 4));
        kv_go[t] = (size_t)r * KD + (cu << 3);
    }

    auto load_kv = [&](int kt, int stg) {
        const int kb = kt << 6;
        const uint32_t so = sb + 32768 + ((uint32_t)stg << 15);
        #pragma unroll
        for (int t = 0; t < 2; t++) {
            const size_t go = kv_go[t] + (size_t)kb * KD;
            cp16(so + kv_sw[t],         kh + go);
            cp16(so + 8192  + kv_sw[t], kl + go);
            cp16(so + 16384 + kv_sw[t], vh + go);
            cp16(so + 24576 + kv_sw[t], vl + go);
        }
        CP_COMMIT();
    };

    // ---- load Q tile (hi/lo) into SMEM (regular loads, once) ----
    #pragma unroll
    for (int t = 0; t < 4; t++) {
        const int u  = tid + (t << 8);
        const int r  = u >> 3;
        const int cu = u & 7;
        const uint32_t sw = swz((r << 7) + (cu << 4));
        const size_t go = (size_t)(qb + r) * KD + (cu << 3);
        *reinterpret_cast<uint4*>(smem + sw) =
            *reinterpret_cast<const uint4*>(qh + go);
        *reinterpret_cast<uint4*>(smem + 16384 + sw) =
            *reinterpret_cast<const uint4*>(ql + go);
    }
    load_kv(0, 0);
    __syncthreads();

    // ---- Q fragments resident in registers (A pattern) ----
    uint32_t aqh[4][4], aql[4][4];
    {
        const int arow = (wid << 4) + (lane & 15);
        #pragma unroll
        for (int kg = 0; kg < 4; kg++) {
            const uint32_t sw = swz((uint32_t)(arow << 7) +
                                    (((kg << 4) + ((lane >> 4) << 3)) << 1));
            ldmx4(sb + sw,         aqh[kg][0], aqh[kg][1], aqh[kg][2], aqh[kg][3]);
            ldmx4(sb + 16384 + sw, aql[kg][0], aql[kg][1], aql[kg][2], aql[kg][3]);
        }
    }

    float m0 = -1e30f, m1 = -1e30f, l0 = 0.f, l1 = 0.f;
    float o[8][4];
    #pragma unroll
    for (int nt = 0; nt < 8; nt++)
        #pragma unroll
        for (int e = 0; e < 4; e++) o[nt][e] = 0.f;

    const int b_row_l = (lane & 7) + ((lane >> 4) << 3);
    const int b_col_l = ((lane >> 3) & 1) << 3;

    for (int kt = 0; kt < 32; kt++) {
        const int kb = kt << 6;
        if (kt + 1 < 32) { load_kv(kt + 1, (kt + 1) & 1); CP_WAIT1(); }
        else             { CP_WAIT0(); }
        __syncthreads();

        const uint32_t kvb = sb + 32768 + ((uint32_t)(kt & 1) << 15);

        // ---- S = Q K^T (3-term) ----
        float s[8][4];
        #pragma unroll
        for (int nt = 0; nt < 8; nt++)
            #pragma unroll
            for (int e = 0; e < 4; e++) s[nt][e] = 0.f;

        #pragma unroll
        for (int kg = 0; kg < 4; kg++) {
            uint32_t kbh[8][2], kbl[8][2];
            #pragma unroll
            for (int ntp = 0; ntp < 4; ntp++) {
                const int krow = (ntp << 4) + b_row_l;
                const uint32_t sw = swz((uint32_t)(krow << 7) +
                                        (((kg << 4) + b_col_l) << 1));
                ldmx4(kvb + sw, kbh[2 * ntp][0], kbh[2 * ntp][1],
                      kbh[2 * ntp + 1][0], kbh[2 * ntp + 1][1]);
                ldmx4(kvb + 8192 + sw, kbl[2 * ntp][0], kbl[2 * ntp][1],
                      kbl[2 * ntp + 1][0], kbl[2 * ntp + 1][1]);
            }
            #pragma unroll
            for (int nt = 0; nt < 8; nt++) {
                mma16816(s[nt], aqh[kg][0], aqh[kg][1], aqh[kg][2], aqh[kg][3],
                         kbh[nt][0], kbh[nt][1]);
                mma16816(s[nt], aqh[kg][0], aqh[kg][1], aqh[kg][2], aqh[kg][3],
                         kbl[nt][0], kbl[nt][1]);
                mma16816(s[nt], aql[kg][0], aql[kg][1], aql[kg][2], aql[kg][3],
                         kbh[nt][0], kbh[nt][1]);
            }
        }

        // ---- diagonal self-mask ----
        if ((kt >> 1) == qt) {
            const int rg = qb + (wid << 4) + (lane >> 2);
            #pragma unroll
            for (int nt = 0; nt < 8; nt++) {
                const int cg = kb + (nt << 3) + ((lane & 3) << 1);
                if (rg == cg)         s[nt][0] = -1e30f;
                if (rg == cg + 1)     s[nt][1] = -1e30f;
                if (rg + 8 == cg)     s[nt][2] = -1e30f;
                if (rg + 8 == cg + 1) s[nt][3] = -1e30f;
            }
        }

        // ---- online softmax (warp-local, quad reductions) ----
        float mt0 = -1e30f, mt1 = -1e30f;
        #pragma unroll
        for (int nt = 0; nt < 8; nt++) {
            mt0 = fmaxf(mt0, fmaxf(s[nt][0], s[nt][1]));
            mt1 = fmaxf(mt1, fmaxf(s[nt][2], s[nt][3]));
        }
        mt0 = fmaxf(mt0, __shfl_xor_sync(0xffffffffu, mt0, 1));
        mt0 = fmaxf(mt0, __shfl_xor_sync(0xffffffffu, mt0, 2));
        mt1 = fmaxf(mt1, __shfl_xor_sync(0xffffffffu, mt1, 1));
        mt1 = fmaxf(mt1, __shfl_xor_sync(0xffffffffu, mt1, 2));

        const float mn0 = fmaxf(m0, mt0);
        const float mn1 = fmaxf(m1, mt1);
        const float al0 = __expf(m0 - mn0);
        const float al1 = __expf(m1 - mn1);
        m0 = mn0; m1 = mn1;

        float ps0 = 0.f, ps1 = 0.f;
        uint32_t ph[4][4], pl[4][4];
        #pragma unroll
        for (int nt = 0; nt < 8; nt++) {
            const float p0 = __expf(s[nt][0] - mn0);
            const float p1 = __expf(s[nt][1] - mn0);
            const float p2 = __expf(s[nt][2] - mn1);
            const float p3 = __expf(s[nt][3] - mn1);
            ps0 += p0 + p1;
            ps1 += p2 + p3;
            const float h0 = bfr(p0), h1 = bfr(p1), h2 = bfr(p2), h3 = bfr(p3);
            const int kg  = nt >> 1;
            const int ix  = (nt & 1) << 1;
            ph[kg][ix]     = packbf(h0, h1);
            ph[kg][ix + 1] = packbf(h2, h3);
            pl[kg][ix]     = packbf(p0 - h0, p1 - h1);
            pl[kg][ix + 1] = packbf(p2 - h2, p3 - h3);
        }
        ps0 += __shfl_xor_sync(0xffffffffu, ps0, 1);
        ps0 += __shfl_xor_sync(0xffffffffu, ps0, 2);
        ps1 += __shfl_xor_sync(0xffffffffu, ps1, 1);
        ps1 += __shfl_xor_sync(0xffffffffu, ps1, 2);
        l0 = l0 * al0 + ps0;
        l1 = l1 * al1 + ps1;

        #pragma unroll
        for (int nt = 0; nt < 8; nt++) {
            o[nt][0] *= al0;
            o[nt][1] *= al0;
            o[nt][2] *= al1;
            o[nt][3] *= al1;
        }

        // ---- O += P V (3-term); trans-loaded V fragments ----
        #pragma unroll
        for (int kg = 0; kg < 4; kg++) {
            uint32_t vbh[8][2], vbl[8][2];
            #pragma unroll
            for (int ntp = 0; ntp < 4; ntp++) {
                const uint32_t sw = swz(
                    (uint32_t)((((kg << 4) + (lane & 15)) << 7)) +
                    (((ntp << 4) + ((lane >> 4) << 3)) << 1));
                ldmx4t(kvb + 16384 + sw, vbh[2 * ntp][0], vbh[2 * ntp][1],
                       vbh[2 * ntp + 1][0], vbh[2 * ntp + 1][1]);
                ldmx4t(kvb + 24576 + sw, vbl[2 * ntp][0], vbl[2 * ntp][1],
                       vbl[2 * ntp + 1][0], vbl[2 * ntp + 1][1]);
            }
            #pragma unroll
            for (int nt = 0; nt < 8; nt++) {
                mma16816(o[nt], ph[kg][0], ph[kg][1], ph[kg][2], ph[kg][3],
                         vbh[nt][0], vbh[nt][1]);
                mma16816(o[nt], pl[kg][0], pl[kg][1], pl[kg][2], pl[kg][3],
                         vbh[nt][0], vbh[nt][1]);
                mma16816(o[nt], ph[kg][0], ph[kg][1], ph[kg][2], ph[kg][3],
                         vbl[nt][0], vbl[nt][1]);
            }
        }
        __syncthreads();   // protect this KV stage from iter kt+1's prefetch
    }

    // ---- epilogue: normalize, split hi/lo, write [b*l][h*d] ----
    const float inv0 = 1.f / l0;
    const float inv1 = 1.f / l1;
    const int b_ = bh >> 4, h_ = bh & 15;
    const int rg0 = qb + (wid << 4) + (lane >> 2);
    uint32_t* Ah = (uint32_t*)g_ah;
    uint32_t* Al = (uint32_t*)g_al;

    #pragma unroll
    for (int nt = 0; nt < 8; nt++) {
        const int d = (nt << 3) + ((lane & 3) << 1);
        const size_t o0 = ((size_t)(b_ << 11) + rg0) * KDIM + (h_ << 6) + d;
        const size_t o1 = o0 + (size_t)8 * KDIM;
        const float w0 = o[nt][0] * inv0, w1 = o[nt][1] * inv0;
        const float w2 = o[nt][2] * inv1, w3 = o[nt][3] * inv1;
        const float h0 = bfr(w0), h1 = bfr(w1), h2 = bfr(w2), h3 = bfr(w3);
        Ah[o0 >> 1] = packbf(h0, h1);
        Al[o0 >> 1] = packbf(w0 - h0, w1 - h1);
        Ah[o1 >> 1] = packbf(h2, h3);
        Al[o1 >> 1] = packbf(w2 - h2, w3 - h3);
    }
}

// ---------------------------------------------------------------------------

extern "C" void kernel_launch(void* const* d_in, const int* in_sizes, int n_in,
                              void* d_out, int out_size)
{
    const float* x  = (const float*)d_in[0];
    const float* Wq = (const float*)d_in[1];
    const float* Wk = (const float*)d_in[2];
    const float* Wv = (const float*)d_in[3];
    const float* Wo = (const float*)d_in[4];
    float* out = (float*)d_out;

    cudaFuncSetAttribute(mma_gemm,
                         cudaFuncAttributeMaxDynamicSharedMemorySize, GEMM_SMEM);
    cudaFuncSetAttribute(attn_mma,
                         cudaFuncAttributeMaxDynamicSharedMemorySize, ATTN_SMEM);

    // 1. split x into bf16 hi/lo
    split_kernel<<<KM * KDIM / 4 / 256, 256>>>(x);

    // 2. transpose+split all 4 weights (one launch)
    dim3 wgrid(KDIM / 32, KDIM / 32, 4);
    dim3 wblk(32, 8);
    wsplit_kernel<<<wgrid, wblk>>>(Wq, Wk, Wv, Wo);

    // 3. QKV projections -> split bf16 q/k/v
    dim3 g_qkv(KDIM / 128, KM / 128, 3);
    mma_gemm<<<g_qkv, 256, GEMM_SMEM>>>(0, nullptr);

    // 4. flash attention on tensor cores
    dim3 g_attn(KL / 128, KB * KH);
    attn_mma<<<g_attn, 256, ATTN_SMEM>>>();

    // 5. output projection
    dim3 g_out(KDIM / 128, KM / 128, 1);
    mma_gemm<<<g_out, 256, GEMM_SMEM>>>(1, out);
}

// round 8
// speedup vs baseline: 3.2524x; 1.0792x over previous
#include <cuda_runtime.h>
#include <cuda_bf16.h>
#include <cstdint>

// ---------------------------------------------------------------------------
// DiagonnalyMaskedSelfAttention: B=2, L=2048, DIM=1024, H=16, D=64, fp32.
// Round 8: R7 + occupancy fixes:
//  - attn: 64KB smem (Q region overlaid with KV stage1) + launch_bounds(256,2)
//  - gemm: 32KB stages (hi|lo packed per 128B row, K-chunk=32) -> 64KB total
// ---------------------------------------------------------------------------

#define KB   2
#define KL   2048
#define KDIM 1024
#define KH   16
#define KD   64
#define KM   (KB * KL)   // 4096 rows

// ---------------- device scratch (no allocations allowed) ------------------
__device__ __align__(16) __nv_bfloat16 g_xh[KM * KDIM];      // x split hi/lo
__device__ __align__(16) __nv_bfloat16 g_xl[KM * KDIM];
__device__ __align__(16) __nv_bfloat16 g_wh[4][KDIM * KDIM]; // W^T [n][k] hi
__device__ __align__(16) __nv_bfloat16 g_wl[4][KDIM * KDIM]; // W^T [n][k] lo
// q/k/v split hi/lo, layout [b*16+h][l][d]; q pre-scaled by 1/8
__device__ __align__(16) __nv_bfloat16 g_qh[KB * KH * KL * KD];
__device__ __align__(16) __nv_bfloat16 g_ql[KB * KH * KL * KD];
__device__ __align__(16) __nv_bfloat16 g_kh[KB * KH * KL * KD];
__device__ __align__(16) __nv_bfloat16 g_kl[KB * KH * KL * KD];
__device__ __align__(16) __nv_bfloat16 g_vh[KB * KH * KL * KD];
__device__ __align__(16) __nv_bfloat16 g_vl[KB * KH * KL * KD];
__device__ __align__(16) __nv_bfloat16 g_ah[KM * KDIM];      // attn out hi/lo
__device__ __align__(16) __nv_bfloat16 g_al[KM * KDIM];

// ---------------- helpers ---------------------------------------------------
__device__ __forceinline__ uint32_t smem_u32(const void* p) {
    uint32_t a;
    asm("{ .reg .u64 t; cvta.to.shared.u64 t, %1; cvt.u32.u64 %0, t; }"
        : "=r"(a) : "l"(p));
    return a;
}

__device__ __forceinline__ void ldmx4(uint32_t addr, uint32_t& r0, uint32_t& r1,
                                      uint32_t& r2, uint32_t& r3) {
    asm volatile("ldmatrix.sync.aligned.m8n8.x4.shared.b16 {%0,%1,%2,%3}, [%4];"
                 : "=r"(r0), "=r"(r1), "=r"(r2), "=r"(r3) : "r"(addr));
}

__device__ __forceinline__ void ldmx4t(uint32_t addr, uint32_t& r0, uint32_t& r1,
                                       uint32_t& r2, uint32_t& r3) {
    asm volatile("ldmatrix.sync.aligned.m8n8.x4.trans.shared.b16 {%0,%1,%2,%3}, [%4];"
                 : "=r"(r0), "=r"(r1), "=r"(r2), "=r"(r3) : "r"(addr));
}

__device__ __forceinline__ void mma16816(float* c, uint32_t a0, uint32_t a1,
                                         uint32_t a2, uint32_t a3,
                                         uint32_t b0, uint32_t b1) {
    asm volatile(
        "mma.sync.aligned.m16n8k16.row.col.f32.bf16.bf16.f32 "
        "{%0,%1,%2,%3}, {%4,%5,%6,%7}, {%8,%9}, {%0,%1,%2,%3};"
        : "+f"(c[0]), "+f"(c[1]), "+f"(c[2]), "+f"(c[3])
        : "r"(a0), "r"(a1), "r"(a2), "r"(a3), "r"(b0), "r"(b1));
}

__device__ __forceinline__ uint32_t swz(uint32_t bo) {
    return bo ^ ((bo >> 3) & 0x70);
}

__device__ __forceinline__ uint32_t packbf(float lo, float hi) {
    uint32_t r;
    asm("cvt.rn.bf16x2.f32 %0, %1, %2;" : "=r"(r) : "f"(hi), "f"(lo));
    return r;
}

__device__ __forceinline__ float bfr(float v) {
    return __bfloat162float(__float2bfloat16(v));
}

// cp.async (LDGSTS) 16B copy + group ops
__device__ __forceinline__ void cp16(uint32_t saddr, const void* gptr) {
    asm volatile("cp.async.cg.shared.global [%0], [%1], 16;"
                 :: "r"(saddr), "l"(gptr));
}
#define CP_COMMIT()  asm volatile("cp.async.commit_group;" ::: "memory")
#define CP_WAIT1()   asm volatile("cp.async.wait_group 1;"  ::: "memory")
#define CP_WAIT0()   asm volatile("cp.async.wait_group 0;"  ::: "memory")

// ---------------------------------------------------------------------------
// Conversion kernels
// ---------------------------------------------------------------------------

__global__ __launch_bounds__(256) void split_kernel(const float* __restrict__ s)
{
    const int i = blockIdx.x * blockDim.x + threadIdx.x;
    const float4 v = reinterpret_cast<const float4*>(s)[i];
    const float a[4] = {v.x, v.y, v.z, v.w};
    #pragma unroll
    for (int j = 0; j < 4; j++) {
        const __nv_bfloat16 hi = __float2bfloat16(a[j]);
        g_xh[i * 4 + j] = hi;
        g_xl[i * 4 + j] = __float2bfloat16(a[j] - __bfloat162float(hi));
    }
}

__global__ __launch_bounds__(256) void wsplit_kernel(
    const float* __restrict__ W0, const float* __restrict__ W1,
    const float* __restrict__ W2, const float* __restrict__ W3)
{
    __shared__ float t[32][33];
    const int widx = blockIdx.z;
    const float* W = (widx == 0) ? W0 : (widx == 1 ? W1 : (widx == 2 ? W2 : W3));
    const int k0 = blockIdx.y << 5;
    const int n0 = blockIdx.x << 5;
    const int tx = threadIdx.x;
    const int ty = threadIdx.y;
    #pragma unroll
    for (int i = 0; i < 4; i++)
        t[ty + i * 8][tx] = W[(size_t)(k0 + ty + i * 8) * KDIM + n0 + tx];
    __syncthreads();
    __nv_bfloat16* Bh = g_wh[widx];
    __nv_bfloat16* Bl = g_wl[widx];
    #pragma unroll
    for (int i = 0; i < 4; i++) {
        const float v = t[tx][ty + i * 8];
        const __nv_bfloat16 hi = __float2bfloat16(v);
        const size_t o = (size_t)(n0 + ty + i * 8) * KDIM + k0 + tx;
        Bh[o] = hi;
        Bl[o] = __float2bfloat16(v - __bfloat162float(hi));
    }
}

// ---------------------------------------------------------------------------
// Warp-MMA GEMM, 2-stage cp.async pipeline, 32KB stages (2 CTAs/SM).
// Stage layout: A-tile @+0 (16KB), B-tile @+16K (16KB); each tile is
// [128 rows][128B]: bytes 0..63 = hi (32 bf16 of this K-chunk), 64..127 = lo.
// K-chunk = 32, 32 chunks.
// mode 0: A = x split, B = g_w[z]; out -> split bf16 q/k/v ([bh][l][d], q*1/8)
// mode 1: A = attn split, B = g_w[3]; out -> dout fp32 row-major
// ---------------------------------------------------------------------------

#define GEMM_SMEM 65536

__global__ __launch_bounds__(256, 2) void mma_gemm(int mode, float* __restrict__ dout)
{
    extern __shared__ __align__(128) char smem[];
    const uint32_t sb = smem_u32(smem);

    const int tid  = threadIdx.x;
    const int wid  = tid >> 5;
    const int lane = tid & 31;
    const int wm   = wid >> 2;
    const int wn   = wid & 3;

    const int M0 = blockIdx.y << 7;
    const int N0 = blockIdx.x << 7;
    const int z  = blockIdx.z;

    const __nv_bfloat16* Agh = (mode == 0) ? g_xh : g_ah;
    const __nv_bfloat16* Agl = (mode == 0) ? g_xl : g_al;
    const int widx = (mode == 0) ? z : 3;
    const __nv_bfloat16* Bgh = g_wh[widx];
    const __nv_bfloat16* Bgl = g_wl[widx];

    float acc[4][4][4];
    #pragma unroll
    for (int mt = 0; mt < 4; mt++)
        #pragma unroll
        for (int nt = 0; nt < 4; nt++)
            #pragma unroll
            for (int e = 0; e < 4; e++) acc[mt][nt][e] = 0.f;

    const int a_row_l = lane & 15;
    const int a_col_l = (lane >> 4) << 3;                 // 0/8 (bf16)
    const int b_row_l = (lane & 7) + ((lane >> 4) << 3);
    const int b_col_l = ((lane >> 3) & 1) << 3;           // 0/8 (bf16)

    // per-thread stage-load pattern: 8x 16B units (4 A-tile, 4 B-tile)
    // unit j within row: j<4 -> hi bytes j*16, j>=4 -> lo bytes 64+(j-4)*16
    uint32_t ld_sw[8];        // swizzled dst offset within tile
    const __nv_bfloat16* ld_src[8];  // source base (row + hi/lo selected), +k0 later
    #pragma unroll
    for (int t = 0; t < 8; t++) {
        const int u   = tid + ((t & 3) << 8);   // 0..1023 within tile
        const int r   = u >> 3;                 // row 0..127
        const int j   = u & 7;                  // 16B unit in row
        const bool bt = (t >= 4);               // B tile?
        ld_sw[t] = (bt ? 16384u : 0u) + swz((r << 7) + (j << 4));
        const size_t rowoff = (size_t)((bt ? N0 : M0) + r) * KDIM + ((j & 3) << 3);
        ld_src[t] = (j < 4) ? ((bt ? Bgh : Agh) + rowoff)
                            : ((bt ? Bgl : Agl) + rowoff);
    }

    auto load_chunk = [&](int c, int stg) {
        const int k0 = c << 5;
        const uint32_t so = sb + ((uint32_t)stg << 15);
        #pragma unroll
        for (int t = 0; t < 8; t++)
            cp16(so + ld_sw[t], ld_src[t] + k0);
        CP_COMMIT();
    };

    load_chunk(0, 0);

    for (int c = 0; c < 32; c++) {
        if (c + 1 < 32) { load_chunk(c + 1, (c + 1) & 1); CP_WAIT1(); }
        else            { CP_WAIT0(); }
        __syncthreads();

        const uint32_t stb = sb + ((uint32_t)(c & 1) << 15);

        #pragma unroll
        for (int ks = 0; ks < 2; ks++) {
            const int kbb = (ks << 5);   // k byte base within 64B hi half

            uint32_t bhf[4][2], blf[4][2];
            #pragma unroll
            for (int ntp = 0; ntp < 2; ntp++) {
                const int brow = wn * 32 + ntp * 16 + b_row_l;
                const uint32_t co = kbb + (b_col_l << 1);
                ldmx4(stb + 16384 + swz((uint32_t)(brow << 7) + co),
                      bhf[2 * ntp][0], bhf[2 * ntp][1],
                      bhf[2 * ntp + 1][0], bhf[2 * ntp + 1][1]);
                ldmx4(stb + 16384 + swz((uint32_t)(brow << 7) + 64 + co),
                      blf[2 * ntp][0], blf[2 * ntp][1],
                      blf[2 * ntp + 1][0], blf[2 * ntp + 1][1]);
            }

            #pragma unroll
            for (int mt = 0; mt < 4; mt++) {
                const int arow = wm * 64 + mt * 16 + a_row_l;
                const uint32_t co = kbb + (a_col_l << 1);
                uint32_t ah0, ah1, ah2, ah3, al0, al1, al2, al3;
                ldmx4(stb + swz((uint32_t)(arow << 7) + co),      ah0, ah1, ah2, ah3);
                ldmx4(stb + swz((uint32_t)(arow << 7) + 64 + co), al0, al1, al2, al3);
                #pragma unroll
                for (int nt = 0; nt < 4; nt++) {
                    mma16816(acc[mt][nt], ah0, ah1, ah2, ah3, bhf[nt][0], bhf[nt][1]);
                    mma16816(acc[mt][nt], ah0, ah1, ah2, ah3, blf[nt][0], blf[nt][1]);
                    mma16816(acc[mt][nt], al0, al1, al2, al3, bhf[nt][0], bhf[nt][1]);
                }
            }
        }
        __syncthreads();   // protect this stage from iter c+1's prefetch
    }

    const int rl = lane >> 2;
    const int cl = (lane & 3) << 1;

    if (mode == 1) {
        #pragma unroll
        for (int mt = 0; mt < 4; mt++)
            #pragma unroll
            for (int nt = 0; nt < 4; nt++) {
                const int col = N0 + wn * 32 + nt * 8 + cl;
                #pragma unroll
                for (int half = 0; half < 2; half++) {
                    const int row = M0 + wm * 64 + mt * 16 + rl + half * 8;
                    *reinterpret_cast<float2*>(dout + (size_t)row * KDIM + col) =
                        make_float2(acc[mt][nt][half * 2], acc[mt][nt][half * 2 + 1]);
                }
            }
        return;
    }

    const float qs = (z == 0) ? 0.125f : 1.0f;
    uint32_t* Oh = (uint32_t*)((z == 0) ? g_qh : (z == 1 ? g_kh : g_vh));
    uint32_t* Ol = (uint32_t*)((z == 0) ? g_ql : (z == 1 ? g_kl : g_vl));

    #pragma unroll
    for (int mt = 0; mt < 4; mt++)
        #pragma unroll
        for (int nt = 0; nt < 4; nt++) {
            const int col = N0 + wn * 32 + nt * 8 + cl;
            const int h = col >> 6, d = col & 63;
            #pragma unroll
            for (int half = 0; half < 2; half++) {
                const int row = M0 + wm * 64 + mt * 16 + rl + half * 8;
                const int b = row >> 11, l = row & 2047;
                const float v0 = acc[mt][nt][half * 2] * qs;
                const float v1 = acc[mt][nt][half * 2 + 1] * qs;
                const float h0 = bfr(v0), h1 = bfr(v1);
                const size_t off = (((size_t)((b << 4) + h) << 11) + l) * 64 + d;
                Oh[off >> 1] = packbf(h0, h1);
                Ol[off >> 1] = packbf(v0 - h0, v1 - h1);
            }
        }
}

// ---------------------------------------------------------------------------
// Flash attention on mma.sync, 2-stage cp.async KV pipeline, 64KB smem.
// Stage s (32KB) @ sb + s*32K: kh@+0 kl@+8K vh@+16K vl@+24K (64x64 SW128).
// Q (32KB, hi@+0 lo@+16K of stage1 region) is staged ONCE in stage1's space,
// consumed into registers before stage1 is first written (kt=1 prefetch).
// ---------------------------------------------------------------------------

#define ATTN_SMEM 65536

__global__ __launch_bounds__(256, 2) void attn_mma()
{
    extern __shared__ __align__(128) char smem[];
    const uint32_t sb = smem_u32(smem);

    const int tid  = threadIdx.x;
    const int wid  = tid >> 5;
    const int lane = tid & 31;

    const int qt = blockIdx.x;
    const int bh = blockIdx.y;
    const int qb = qt << 7;

    const __nv_bfloat16* qh = g_qh + ((size_t)bh << 11) * KD;
    const __nv_bfloat16* ql = g_ql + ((size_t)bh << 11) * KD;
    const __nv_bfloat16* kh = g_kh + ((size_t)bh << 11) * KD;
    const __nv_bfloat16* kl = g_kl + ((size_t)bh << 11) * KD;
    const __nv_bfloat16* vh = g_vh + ((size_t)bh << 11) * KD;
    const __nv_bfloat16* vl = g_vl + ((size_t)bh << 11) * KD;

    uint32_t kv_sw[2];
    size_t   kv_go[2];
    #pragma unroll
    for (int t = 0; t < 2; t++) {
        const int u  = tid + (t << 8);
        const int r  = u >> 3;
        const int cu = u & 7;
        kv_sw[t] = swz((r << 7) + (cu << 4));
        kv_go[t] = (size_t)r * KD + (cu << 3);
    }

    auto load_kv = [&](int kt, int stg) {
        const int kb = kt << 6;
        const uint32_t so = sb + ((uint32_t)stg << 15);
        #pragma unroll
        for (int t = 0; t < 2; t++) {
            const size_t go = kv_go[t] + (size_t)kb * KD;
            cp16(so + kv_sw[t],         kh + go);
            cp16(so + 8192  + kv_sw[t], kl + go);
            cp16(so + 16384 + kv_sw[t], vh + go);
            cp16(so + 24576 + kv_sw[t], vl + go);
        }
        CP_COMMIT();
    };

    // ---- stage Q (hi/lo) into stage-1 region; prefetch KV tile 0 ----
    load_kv(0, 0);
    #pragma unroll
    for (int t = 0; t < 4; t++) {
        const int u  = tid + (t << 8);
        const int r  = u >> 3;
        const int cu = u & 7;
        const uint32_t sw = swz((r << 7) + (cu << 4));
        const size_t go = (size_t)(qb + r) * KD + (cu << 3);
        *reinterpret_cast<uint4*>(smem + 32768 + sw) =
            *reinterpret_cast<const uint4*>(qh + go);
        *reinterpret_cast<uint4*>(smem + 49152 + sw) =
            *reinterpret_cast<const uint4*>(ql + go);
    }
    __syncthreads();

    // ---- Q fragments -> registers (A pattern) ----
    uint32_t aqh[4][4], aql[4][4];
    {
        const int arow = (wid << 4) + (lane & 15);
        #pragma unroll
        for (int kg = 0; kg < 4; kg++) {
            const uint32_t sw = swz((uint32_t)(arow << 7) +
                                    (((kg << 4) + ((lane >> 4) << 3)) << 1));
            ldmx4(sb + 32768 + sw, aqh[kg][0], aqh[kg][1], aqh[kg][2], aqh[kg][3]);
            ldmx4(sb + 49152 + sw, aql[kg][0], aql[kg][1], aql[kg][2], aql[kg][3]);
        }
    }
    __syncthreads();   // everyone done reading Q before stage1 gets overwritten

    float m0 = -1e30f, m1 = -1e30f, l0 = 0.f, l1 = 0.f;
    float o[8][4];
    #pragma unroll
    for (int nt = 0; nt < 8; nt++)
        #pragma unroll
        for (int e = 0; e < 4; e++) o[nt][e] = 0.f;

    const int b_row_l = (lane & 7) + ((lane >> 4) << 3);
    const int b_col_l = ((lane >> 3) & 1) << 3;

    for (int kt = 0; kt < 32; kt++) {
        const int kb = kt << 6;
        if (kt + 1 < 32) { load_kv(kt + 1, (kt + 1) & 1); CP_WAIT1(); }
        else             { CP_WAIT0(); }
        __syncthreads();

        const uint32_t kvb = sb + ((uint32_t)(kt & 1) << 15);

        // ---- S = Q K^T (3-term) ----
        float s[8][4];
        #pragma unroll
        for (int nt = 0; nt < 8; nt++)
            #pragma unroll
            for (int e = 0; e < 4; e++) s[nt][e] = 0.f;

        #pragma unroll
        for (int kg = 0; kg < 4; kg++) {
            uint32_t kbh[8][2], kbl[8][2];
            #pragma unroll
            for (int ntp = 0; ntp < 4; ntp++) {
                const int krow = (ntp << 4) + b_row_l;
                const uint32_t sw = swz((uint32_t)(krow << 7) +
                                        (((kg << 4) + b_col_l) << 1));
                ldmx4(kvb + sw, kbh[2 * ntp][0], kbh[2 * ntp][1],
                      kbh[2 * ntp + 1][0], kbh[2 * ntp + 1][1]);
                ldmx4(kvb + 8192 + sw, kbl[2 * ntp][0], kbl[2 * ntp][1],
                      kbl[2 * ntp + 1][0], kbl[2 * ntp + 1][1]);
            }
            #pragma unroll
            for (int nt = 0; nt < 8; nt++) {
                mma16816(s[nt], aqh[kg][0], aqh[kg][1], aqh[kg][2], aqh[kg][3],
                         kbh[nt][0], kbh[nt][1]);
                mma16816(s[nt], aqh[kg][0], aqh[kg][1], aqh[kg][2], aqh[kg][3],
                         kbl[nt][0], kbl[nt][1]);
                mma16816(s[nt], aql[kg][0], aql[kg][1], aql[kg][2], aql[kg][3],
                         kbh[nt][0], kbh[nt][1]);
            }
        }

        // ---- diagonal self-mask ----
        if ((kt >> 1) == qt) {
            const int rg = qb + (wid << 4) + (lane >> 2);
            #pragma unroll
            for (int nt = 0; nt < 8; nt++) {
                const int cg = kb + (nt << 3) + ((lane & 3) << 1);
                if (rg == cg)         s[nt][0] = -1e30f;
                if (rg == cg + 1)     s[nt][1] = -1e30f;
                if (rg + 8 == cg)     s[nt][2] = -1e30f;
                if (rg + 8 == cg + 1) s[nt][3] = -1e30f;
            }
        }

        // ---- online softmax (warp-local quad reductions) ----
        float mt0 = -1e30f, mt1 = -1e30f;
        #pragma unroll
        for (int nt = 0; nt < 8; nt++) {
            mt0 = fmaxf(mt0, fmaxf(s[nt][0], s[nt][1]));
            mt1 = fmaxf(mt1, fmaxf(s[nt][2], s[nt][3]));
        }
        mt0 = fmaxf(mt0, __shfl_xor_sync(0xffffffffu, mt0, 1));
        mt0 = fmaxf(mt0, __shfl_xor_sync(0xffffffffu, mt0, 2));
        mt1 = fmaxf(mt1, __shfl_xor_sync(0xffffffffu, mt1, 1));
        mt1 = fmaxf(mt1, __shfl_xor_sync(0xffffffffu, mt1, 2));

        const float mn0 = fmaxf(m0, mt0);
        const float mn1 = fmaxf(m1, mt1);
        const float al0 = __expf(m0 - mn0);
        const float al1 = __expf(m1 - mn1);
        m0 = mn0; m1 = mn1;

        float ps0 = 0.f, ps1 = 0.f;
        uint32_t ph[4][4], pl[4][4];
        #pragma unroll
        for (int nt = 0; nt < 8; nt++) {
            const float p0 = __expf(s[nt][0] - mn0);
            const float p1 = __expf(s[nt][1] - mn0);
            const float p2 = __expf(s[nt][2] - mn1);
            const float p3 = __expf(s[nt][3] - mn1);
            ps0 += p0 + p1;
            ps1 += p2 + p3;
            const float h0 = bfr(p0), h1 = bfr(p1), h2 = bfr(p2), h3 = bfr(p3);
            const int kg  = nt >> 1;
            const int ix  = (nt & 1) << 1;
            ph[kg][ix]     = packbf(h0, h1);
            ph[kg][ix + 1] = packbf(h2, h3);
            pl[kg][ix]     = packbf(p0 - h0, p1 - h1);
            pl[kg][ix + 1] = packbf(p2 - h2, p3 - h3);
        }
        ps0 += __shfl_xor_sync(0xffffffffu, ps0, 1);
        ps0 += __shfl_xor_sync(0xffffffffu, ps0, 2);
        ps1 += __shfl_xor_sync(0xffffffffu, ps1, 1);
        ps1 += __shfl_xor_sync(0xffffffffu, ps1, 2);
        l0 = l0 * al0 + ps0;
        l1 = l1 * al1 + ps1;

        #pragma unroll
        for (int nt = 0; nt < 8; nt++) {
            o[nt][0] *= al0;
            o[nt][1] *= al0;
            o[nt][2] *= al1;
            o[nt][3] *= al1;
        }

        // ---- O += P V (3-term); trans-loaded V fragments ----
        #pragma unroll
        for (int kg = 0; kg < 4; kg++) {
            uint32_t vbh[8][2], vbl[8][2];
            #pragma unroll
            for (int ntp = 0; ntp < 4; ntp++) {
                const uint32_t sw = swz(
                    (uint32_t)((((kg << 4) + (lane & 15)) << 7)) +
                    (((ntp << 4) + ((lane >> 4) << 3)) << 1));
                ldmx4t(kvb + 16384 + sw, vbh[2 * ntp][0], vbh[2 * ntp][1],
                       vbh[2 * ntp + 1][0], vbh[2 * ntp + 1][1]);
                ldmx4t(kvb + 24576 + sw, vbl[2 * ntp][0], vbl[2 * ntp][1],
                       vbl[2 * ntp + 1][0], vbl[2 * ntp + 1][1]);
            }
            #pragma unroll
            for (int nt = 0; nt < 8; nt++) {
                mma16816(o[nt], ph[kg][0], ph[kg][1], ph[kg][2], ph[kg][3],
                         vbh[nt][0], vbh[nt][1]);
                mma16816(o[nt], pl[kg][0], pl[kg][1], pl[kg][2], pl[kg][3],
                         vbh[nt][0], vbh[nt][1]);
                mma16816(o[nt], ph[kg][0], ph[kg][1], ph[kg][2], ph[kg][3],
                         vbl[nt][0], vbl[nt][1]);
            }
        }
        __syncthreads();   // protect this KV stage from iter kt+1's prefetch
    }

    // ---- epilogue: normalize, split hi/lo, write [b*l][h*d] ----
    const float inv0 = 1.f / l0;
    const float inv1 = 1.f / l1;
    const int b_ = bh >> 4, h_ = bh & 15;
    const int rg0 = qb + (wid << 4) + (lane >> 2);
    uint32_t* Ah = (uint32_t*)g_ah;
    uint32_t* Al = (uint32_t*)g_al;

    #pragma unroll
    for (int nt = 0; nt < 8; nt++) {
        const int d = (nt << 3) + ((lane & 3) << 1);
        const size_t o0 = ((size_t)(b_ << 11) + rg0) * KDIM + (h_ << 6) + d;
        const size_t o1 = o0 + (size_t)8 * KDIM;
        const float w0 = o[nt][0] * inv0, w1 = o[nt][1] * inv0;
        const float w2 = o[nt][2] * inv1, w3 = o[nt][3] * inv1;
        const float h0 = bfr(w0), h1 = bfr(w1), h2 = bfr(w2), h3 = bfr(w3);
        Ah[o0 >> 1] = packbf(h0, h1);
        Al[o0 >> 1] = packbf(w0 - h0, w1 - h1);
        Ah[o1 >> 1] = packbf(h2, h3);
        Al[o1 >> 1] = packbf(w2 - h2, w3 - h3);
    }
}

// ---------------------------------------------------------------------------

extern "C" void kernel_launch(void* const* d_in, const int* in_sizes, int n_in,
                              void* d_out, int out_size)
{
    const float* x  = (const float*)d_in[0];
    const float* Wq = (const float*)d_in[1];
    const float* Wk = (const float*)d_in[2];
    const float* Wv = (const float*)d_in[3];
    const float* Wo = (const float*)d_in[4];
    float* out = (float*)d_out;

    cudaFuncSetAttribute(mma_gemm,
                         cudaFuncAttributeMaxDynamicSharedMemorySize, GEMM_SMEM);
    cudaFuncSetAttribute(attn_mma,
                         cudaFuncAttributeMaxDynamicSharedMemorySize, ATTN_SMEM);

    // 1. split x into bf16 hi/lo
    split_kernel<<<KM * KDIM / 4 / 256, 256>>>(x);

    // 2. transpose+split all 4 weights (one launch)
    dim3 wgrid(KDIM / 32, KDIM / 32, 4);
    dim3 wblk(32, 8);
    wsplit_kernel<<<wgrid, wblk>>>(Wq, Wk, Wv, Wo);

    // 3. QKV projections -> split bf16 q/k/v
    dim3 g_qkv(KDIM / 128, KM / 128, 3);
    mma_gemm<<<g_qkv, 256, GEMM_SMEM>>>(0, nullptr);

    // 4. flash attention on tensor cores
    dim3 g_attn(KL / 128, KB * KH);
    attn_mma<<<g_attn, 256, ATTN_SMEM>>>();

    // 5. output projection
    dim3 g_out(KDIM / 128, KM / 128, 1);
    mma_gemm<<<g_out, 256, GEMM_SMEM>>>(1, out);
}